// round 3
// baseline (speedup 1.0000x reference)
#include <cuda_runtime.h>

#define Bq 32
#define Cc 64
#define Nn 1024

typedef unsigned long long ull;

// ---------------- scratch (device globals) ----------------------------------
__device__ float g_phiT[Bq * Nn * Cc];    // [b][m][c]   phi^T
__device__ float g_theta[Bq * Cc * Nn];   // [b][c][n]   theta^T
__device__ float g_gm[Bq * Cc * Nn];      // [b][c][n]   (w_mv@w_g) @ x
__device__ float g_P[Bq * Cc * Nn];       // [b][c][k]   P = phi @ w_mk^T (RED target)
__device__ float g_E[Bq * Nn * Nn];       // [b][k][n]   exp(att)^T  (128 MB)
__device__ float g_Z[Bq * Nn];            // col sums of exp(att) over n
__device__ float g_wgv[Cc * Cc];          // w_mv @ w_g
__device__ float g_wmkT[Nn * Nn];         // w_mk^T
__device__ float g_gmz2[Bq * Nn * Cc];    // [b][m][o]  (w_mask@gm)/Z folded

// ---------------- f32x2 helpers ---------------------------------------------
__device__ __forceinline__ ull pk2(float lo, float hi) {
    ull r;
    asm("mov.b64 %0, {%1, %2};" : "=l"(r) : "f"(lo), "f"(hi));
    return r;
}
__device__ __forceinline__ void fma2(ull& d, ull a, ull b) {
    asm("fma.rn.f32x2 %0, %1, %2, %0;" : "+l"(d) : "l"(a), "l"(b));
}
__device__ __forceinline__ float2 upk2(ull v) {
    float2 r;
    asm("mov.b64 {%0, %1}, %2;" : "=f"(r.x), "=f"(r.y) : "l"(v));
    return r;
}

#define FMA_ROW8(acc, kv, b0, b1)                                    \
    do {                                                             \
        _Pragma("unroll")                                            \
        for (int _i = 0; _i < 8; _i++) {                             \
            ull _a = pk2(kv[_i], kv[_i]);                            \
            fma2(acc[_i][0], _a, b0.x); fma2(acc[_i][1], _a, b0.y);  \
            fma2(acc[_i][2], _a, b1.x); fma2(acc[_i][3], _a, b1.y);  \
        }                                                            \
    } while (0)

// ---------------- K0: zero Z + P, wgv = w_mv @ w_g --------------------------
// grid 1024 x 256
__global__ void k0_prep(const float* __restrict__ wmv, const float* __restrict__ wg) {
    int t = blockIdx.x * blockDim.x + threadIdx.x;   // 0..262143
    float4 z = make_float4(0.f, 0.f, 0.f, 0.f);
    ((float4*)g_P)[t] = z;                 // 2M floats = 524288 float4
    ((float4*)g_P)[t + 262144] = z;
    if (t < Bq * Nn) g_Z[t] = 0.0f;
    if (t < Cc * Cc) {
        int d = t >> 6, ci = t & 63;
        float s = 0.0f;
#pragma unroll
        for (int c = 0; c < 64; c++) s += wmv[d * 64 + c] * wg[c * 64 + ci];
        g_wgv[t] = s;
    }
}

// ---------------- K0t: wmkT[m][k] = wmk[k][m] -------------------------------
__global__ __launch_bounds__(256) void k0t_transpose(const float* __restrict__ wmk) {
    __shared__ float tl[32][33];
    int r0 = blockIdx.y << 5, c0 = blockIdx.x << 5;
    int t = threadIdx.x, c = t & 31, r = t >> 5;
#pragma unroll
    for (int i = 0; i < 4; i++)
        tl[r + i * 8][c] = wmk[(r0 + r + i * 8) * Nn + c0 + c];
    __syncthreads();
#pragma unroll
    for (int i = 0; i < 4; i++)
        g_wmkT[(c0 + r + i * 8) * Nn + r0 + c] = tl[c][r + i * 8];
}

// ---------------- K1: channel GEMMs: phiT, theta, gm ------------------------
__global__ __launch_bounds__(256) void k1_channel(
    const float* __restrict__ x, const float* __restrict__ wphi,
    const float* __restrict__ wtheta) {
    __shared__ __align__(16) float sX[64][68];   // [ci][nn]
    __shared__ __align__(16) float sW[64][68];   // [ci][c]
    int b = blockIdx.x, n0 = blockIdx.y << 6;
    int t = threadIdx.x, ty = t >> 4, tx = t & 15;

#pragma unroll
    for (int i = 0; i < 16; i++) {
        int idx = t + (i << 8);
        int ci = idx >> 6, nn = idx & 63;
        sX[ci][nn] = x[((b << 6) + ci) * Nn + n0 + nn];
    }

    const float* Ws[3] = {wphi, wtheta, g_wgv};

    for (int p = 0; p < 3; p++) {
        __syncthreads();
#pragma unroll
        for (int i = 0; i < 16; i++) {
            int idx = t + (i << 8);
            int c = idx >> 6, ci = idx & 63;
            sW[ci][c] = Ws[p][idx];
        }
        __syncthreads();

        ull acc[4][2] = {};
#pragma unroll 8
        for (int ci = 0; ci < 64; ci++) {
            float4 av = *(const float4*)&sW[ci][ty << 2];
            ulonglong2 bv = *(const ulonglong2*)&sX[ci][tx << 2];
            ull a0 = pk2(av.x, av.x), a1 = pk2(av.y, av.y);
            ull a2 = pk2(av.z, av.z), a3 = pk2(av.w, av.w);
            fma2(acc[0][0], a0, bv.x); fma2(acc[0][1], a0, bv.y);
            fma2(acc[1][0], a1, bv.x); fma2(acc[1][1], a1, bv.y);
            fma2(acc[2][0], a2, bv.x); fma2(acc[2][1], a2, bv.y);
            fma2(acc[3][0], a3, bv.x); fma2(acc[3][1], a3, bv.y);
        }
        float v[4][4];
#pragma unroll
        for (int i = 0; i < 4; i++) {
            float2 v0 = upk2(acc[i][0]), v1 = upk2(acc[i][1]);
            v[i][0] = v0.x; v[i][1] = v0.y; v[i][2] = v1.x; v[i][3] = v1.y;
        }
        if (p == 0) {
#pragma unroll
            for (int j = 0; j < 4; j++) {
                *(float4*)&g_phiT[(b * Nn + n0 + (tx << 2) + j) * Cc + (ty << 2)] =
                    make_float4(v[0][j], v[1][j], v[2][j], v[3][j]);
            }
        } else {
            float* O = (p == 1 ? g_theta : g_gm) + (b << 6) * Nn + n0;
#pragma unroll
            for (int i = 0; i < 4; i++)
                *(float4*)&O[((ty << 2) + i) * Nn + (tx << 2)] =
                    make_float4(v[i][0], v[i][1], v[i][2], v[i][3]);
        }
    }
}

// ---------------- K2: P[c][k] += sum_m phiT[m][c] * wmkT[m][k] --------------
// grid (B, N/128, 2 m-splits), block 128, micro 8c x 8k, RED.ADD epilogue
__global__ __launch_bounds__(128, 4) void k2_P(void) {
    __shared__ __align__(16) float sA[32][68];   // [mm][c]
    __shared__ __align__(16) float sB[32][132];  // [mm][kk], k-tile 128
    int b = blockIdx.x, k0 = blockIdx.y << 7, mbase = blockIdx.z << 9;
    int t = threadIdx.x;
    int tx = t >> 3;   // 0..15 -> k group (8 wide)
    int ty = t & 7;    // 0..7  -> c group (8 wide)

    ull acc[8][4] = {};
    for (int m0 = 0; m0 < 512; m0 += 32) {
        __syncthreads();
#pragma unroll
        for (int i = 0; i < 4; i++) {
            int lin = t + (i << 7);
            int r = lin >> 4, c4 = lin & 15;
            *(float4*)&sA[r][c4 << 2] =
                *(const float4*)&g_phiT[(b * Nn + mbase + m0 + r) * Cc + (c4 << 2)];
        }
#pragma unroll
        for (int i = 0; i < 8; i++) {
            int lin = t + (i << 7);
            int r = lin >> 5, c4 = lin & 31;
            *(float4*)&sB[r][c4 << 2] =
                *(const float4*)&g_wmkT[(mbase + m0 + r) * Nn + k0 + (c4 << 2)];
        }
        __syncthreads();
#pragma unroll
        for (int mm = 0; mm < 32; mm++) {
            float4 a0 = *(const float4*)&sA[mm][ty << 3];
            float4 a1 = *(const float4*)&sA[mm][(ty << 3) + 4];
            ulonglong2 b0 = *(const ulonglong2*)&sB[mm][tx << 3];
            ulonglong2 b1 = *(const ulonglong2*)&sB[mm][(tx << 3) + 4];
            float kv[8] = {a0.x, a0.y, a0.z, a0.w, a1.x, a1.y, a1.z, a1.w};
            FMA_ROW8(acc, kv, b0, b1);
        }
    }
    float* Pp = g_P + (b << 6) * Nn;
#pragma unroll
    for (int i = 0; i < 8; i++) {
        int c = (ty << 3) + i;
        float* row = &Pp[c * Nn + k0 + (tx << 3)];
        float2 v0 = upk2(acc[i][0]), v1 = upk2(acc[i][1]);
        float2 v2 = upk2(acc[i][2]), v3 = upk2(acc[i][3]);
        atomicAdd(row + 0, v0.x); atomicAdd(row + 1, v0.y);
        atomicAdd(row + 2, v1.x); atomicAdd(row + 3, v1.y);
        atomicAdd(row + 4, v2.x); atomicAdd(row + 5, v2.y);
        atomicAdd(row + 6, v3.x); atomicAdd(row + 7, v3.y);
    }
}

// ---------------- K3: E_t[k][n] = exp(sum_c theta[c][n] P[c][k]), Z sums ----
// grid (N/128 k, N/128 n, B), block 256, micro 8k x 8n
__global__ __launch_bounds__(256, 2) void k3_att(void) {
    __shared__ __align__(16) float sP[32][132];  // [cc][kk]
    __shared__ __align__(16) float sT[32][132];  // [cc][nn]
    __shared__ float red[128][17];
    int b = blockIdx.z, n0 = blockIdx.y << 7, k0 = blockIdx.x << 7;
    int t = threadIdx.x, ty = t >> 4, tx = t & 15;
    const float* th = g_theta + (b << 6) * Nn;
    const float* Pp = g_P + (b << 6) * Nn;

    ull acc[8][4] = {};
    for (int c0 = 0; c0 < 64; c0 += 32) {
        __syncthreads();
#pragma unroll
        for (int i = 0; i < 4; i++) {
            int idx = t + (i << 8);
            int r = idx >> 5, c4 = idx & 31;
            *(float4*)&sT[r][c4 << 2] = *(const float4*)&th[(c0 + r) * Nn + n0 + (c4 << 2)];
            *(float4*)&sP[r][c4 << 2] = *(const float4*)&Pp[(c0 + r) * Nn + k0 + (c4 << 2)];
        }
        __syncthreads();
#pragma unroll
        for (int cc = 0; cc < 32; cc++) {
            float4 a0 = *(const float4*)&sP[cc][ty << 3];
            float4 a1 = *(const float4*)&sP[cc][(ty << 3) + 4];
            ulonglong2 b0 = *(const ulonglong2*)&sT[cc][tx << 2];
            ulonglong2 b1 = *(const ulonglong2*)&sT[cc][64 + (tx << 2)];
            float kv[8] = {a0.x, a0.y, a0.z, a0.w, a1.x, a1.y, a1.z, a1.w};
            FMA_ROW8(acc, kv, b0, b1);
        }
    }
    float* Et = g_E + (b * Nn + k0 + (ty << 3)) * Nn + n0;
#pragma unroll
    for (int i = 0; i < 8; i++) {
        float2 v0 = upk2(acc[i][0]), v1 = upk2(acc[i][1]);
        float2 v2 = upk2(acc[i][2]), v3 = upk2(acc[i][3]);
        float e0 = __expf(v0.x), e1 = __expf(v0.y);
        float e2 = __expf(v1.x), e3 = __expf(v1.y);
        float e4 = __expf(v2.x), e5 = __expf(v2.y);
        float e6 = __expf(v3.x), e7 = __expf(v3.y);
        *(float4*)&Et[i * Nn + (tx << 2)] = make_float4(e0, e1, e2, e3);
        *(float4*)&Et[i * Nn + 64 + (tx << 2)] = make_float4(e4, e5, e6, e7);
        red[(ty << 3) + i][tx] = e0 + e1 + e2 + e3 + e4 + e5 + e6 + e7;
    }
    __syncthreads();
    if (t < 128) {
        float s = 0.0f;
#pragma unroll
        for (int j = 0; j < 16; j++) s += red[t][j];
        atomicAdd(&g_Z[b * Nn + k0 + t], s);
    }
}

// ---------------- K5: gmz2[m][o] = (sum_c wmask[o][c] gm[c][m]) / Z[m] ------
__global__ __launch_bounds__(256) void k5_gmz(const float* __restrict__ wmask) {
    __shared__ __align__(16) float smG[64][68];
    __shared__ __align__(16) float smW[64][68];
    __shared__ float sz[64];
    int b = blockIdx.x, m0 = blockIdx.y << 6;
    int t = threadIdx.x;
    const float* gm = g_gm + (b << 6) * Nn;
#pragma unroll
    for (int i = 0; i < 4; i++) {
        int idx = t + (i << 8);
        int r = idx >> 4, c4 = idx & 15;
        *(float4*)&smG[r][c4 << 2] = *(const float4*)&gm[r * Nn + m0 + (c4 << 2)];
        *(float4*)&smW[r][c4 << 2] = *(const float4*)&wmask[r * 64 + (c4 << 2)];
    }
    if (t < 64) sz[t] = 1.0f / g_Z[b * Nn + m0 + t];
    __syncthreads();
    int m = t & 63, og = t >> 6;
    float inv = sz[m];
    float* dst = &g_gmz2[(b * Nn + m0 + m) * Cc + (og << 4)];
#pragma unroll
    for (int q = 0; q < 4; q++) {
        float r[4];
#pragma unroll
        for (int j = 0; j < 4; j++) {
            int o = (og << 4) + (q << 2) + j;
            float s = 0.0f;
#pragma unroll
            for (int c = 0; c < 64; c++) s += smW[o][c] * smG[c][m];
            r[j] = s * inv;
        }
        *(float4*)&dst[q << 2] = make_float4(r[0], r[1], r[2], r[3]);
    }
}

// ---------------- K4: out[o][n] += sum_m gmz2[m][o] * E_t[m][n] -------------
// grid (B, N/128, 2 m-splits), block 128, micro 8o x 8n, RED into out (= x)
__global__ __launch_bounds__(128, 4) void k4_out(float* __restrict__ out) {
    __shared__ __align__(16) float sG[32][68];   // [mm][o]
    __shared__ __align__(16) float sE[32][132];  // [mm][nn], n-tile 128
    int b = blockIdx.x, n0 = blockIdx.y << 7, mbase = blockIdx.z << 9;
    int t = threadIdx.x;
    int tx = t >> 3;   // 0..15 -> n group (8 wide)
    int ty = t & 7;    // 0..7  -> o group (8 wide)

    ull acc[8][4] = {};
    for (int m0 = 0; m0 < 512; m0 += 32) {
        __syncthreads();
#pragma unroll
        for (int i = 0; i < 4; i++) {
            int lin = t + (i << 7);
            int r = lin >> 4, c4 = lin & 15;
            *(float4*)&sG[r][c4 << 2] =
                *(const float4*)&g_gmz2[(b * Nn + mbase + m0 + r) * Cc + (c4 << 2)];
        }
#pragma unroll
        for (int i = 0; i < 8; i++) {
            int lin = t + (i << 7);
            int r = lin >> 5, c4 = lin & 31;
            *(float4*)&sE[r][c4 << 2] =
                *(const float4*)&g_E[(b * Nn + mbase + m0 + r) * Nn + n0 + (c4 << 2)];
        }
        __syncthreads();
#pragma unroll
        for (int mm = 0; mm < 32; mm++) {
            float4 a0 = *(const float4*)&sG[mm][ty << 3];
            float4 a1 = *(const float4*)&sG[mm][(ty << 3) + 4];
            ulonglong2 b0 = *(const ulonglong2*)&sE[mm][tx << 3];
            ulonglong2 b1 = *(const ulonglong2*)&sE[mm][(tx << 3) + 4];
            float kv[8] = {a0.x, a0.y, a0.z, a0.w, a1.x, a1.y, a1.z, a1.w};
            FMA_ROW8(acc, kv, b0, b1);
        }
    }
#pragma unroll
    for (int i = 0; i < 8; i++) {
        int o = (ty << 3) + i;
        float* row = &out[((b << 6) + o) * Nn + n0 + (tx << 3)];
        float2 v0 = upk2(acc[i][0]), v1 = upk2(acc[i][1]);
        float2 v2 = upk2(acc[i][2]), v3 = upk2(acc[i][3]);
        atomicAdd(row + 0, v0.x); atomicAdd(row + 1, v0.y);
        atomicAdd(row + 2, v1.x); atomicAdd(row + 3, v1.y);
        atomicAdd(row + 4, v2.x); atomicAdd(row + 5, v2.y);
        atomicAdd(row + 6, v3.x); atomicAdd(row + 7, v3.y);
    }
}

// ---------------- launch ----------------------------------------------------
extern "C" void kernel_launch(void* const* d_in, const int* in_sizes, int n_in,
                              void* d_out, int out_size) {
    const float* x      = (const float*)d_in[0];
    const float* wphi   = (const float*)d_in[1];
    const float* wtheta = (const float*)d_in[2];
    const float* wg     = (const float*)d_in[3];
    const float* wmask  = (const float*)d_in[4];
    const float* wmv    = (const float*)d_in[5];
    const float* wmk    = (const float*)d_in[6];
    float* out = (float*)d_out;

    k0_prep<<<1024, 256>>>(wmv, wg);
    k0t_transpose<<<dim3(32, 32), 256>>>(wmk);
    k1_channel<<<dim3(32, 16), 256>>>(x, wphi, wtheta);
    k2_P<<<dim3(32, 8, 2), 128>>>();
    k3_att<<<dim3(8, 8, 32), 256>>>();
    k5_gmz<<<dim3(32, 16), 256>>>(wmask);
    // out = x (residual base), then k4 REDs partial GEMM results on top
    cudaMemcpyAsync(out, x, (size_t)Bq * Cc * Nn * sizeof(float),
                    cudaMemcpyDeviceToDevice);
    k4_out<<<dim3(32, 8, 2), 128>>>(out);
}

// round 5
// speedup vs baseline: 1.4005x; 1.4005x over previous
#include <cuda_runtime.h>
#include <cuda_bf16.h>
#include <cstdint>

#define Bq 32
#define Cc 64
#define Nn 1024

typedef unsigned long long ull;

// ---------------- scratch (device globals) ----------------------------------
__device__ __nv_bfloat16 g_phiH[Bq * Cc * Nn];  // [b][c][m] phi hi
__device__ __nv_bfloat16 g_phiL[Bq * Cc * Nn];  // [b][c][m] phi lo
__device__ __nv_bfloat16 g_wmkH[Nn * Nn];       // [k][m] wmk hi
__device__ __nv_bfloat16 g_wmkL[Nn * Nn];       // [k][m] wmk lo
__device__ float g_theta[Bq * Cc * Nn];   // [b][c][n]
__device__ float g_gm[Bq * Cc * Nn];      // [b][c][n]
__device__ float g_P[Bq * Cc * Nn];       // [b][c][k]
__device__ float g_E[Bq * Nn * Nn];       // [b][k][n] exp(att)^T (128 MB)
__device__ float g_Z[Bq * Nn];
__device__ float g_wgv[Cc * Cc];          // w_mv @ w_g
__device__ float g_gzT[Bq * Cc * Nn];     // [b][o][m]  (w_mask@gm)/Z, row-major o

// ---------------- f32x2 helpers ---------------------------------------------
__device__ __forceinline__ ull pk2(float lo, float hi) {
    ull r;
    asm("mov.b64 %0, {%1, %2};" : "=l"(r) : "f"(lo), "f"(hi));
    return r;
}
__device__ __forceinline__ void fma2(ull& d, ull a, ull b) {
    asm("fma.rn.f32x2 %0, %1, %2, %0;" : "+l"(d) : "l"(a), "l"(b));
}
__device__ __forceinline__ float2 upk2(ull v) {
    float2 r;
    asm("mov.b64 {%0, %1}, %2;" : "=f"(r.x), "=f"(r.y) : "l"(v));
    return r;
}

#define FMA_ROW8(acc, kv, b0, b1)                                    \
    do {                                                             \
        _Pragma("unroll")                                            \
        for (int _i = 0; _i < 8; _i++) {                             \
            ull _a = pk2(kv[_i], kv[_i]);                            \
            fma2(acc[_i][0], _a, b0.x); fma2(acc[_i][1], _a, b0.y);  \
            fma2(acc[_i][2], _a, b1.x); fma2(acc[_i][3], _a, b1.y);  \
        }                                                            \
    } while (0)

// ---------------- mma.sync helpers (baseline ISA, no tcgen05) ---------------
__device__ __forceinline__ uint32_t smem_u32(const void* p) {
    uint32_t a;
    asm("{ .reg .u64 t; cvta.to.shared.u64 t, %1; cvt.u32.u64 %0, t; }"
        : "=r"(a) : "l"(p));
    return a;
}
__device__ __forceinline__ void ldsm_x4(uint32_t addr, uint32_t r[4]) {
    asm volatile("ldmatrix.sync.aligned.m8n8.x4.shared.b16 {%0,%1,%2,%3}, [%4];"
                 : "=r"(r[0]), "=r"(r[1]), "=r"(r[2]), "=r"(r[3]) : "r"(addr));
}
__device__ __forceinline__ void ldsm_x4t(uint32_t addr, uint32_t r[4]) {
    asm volatile("ldmatrix.sync.aligned.m8n8.x4.trans.shared.b16 {%0,%1,%2,%3}, [%4];"
                 : "=r"(r[0]), "=r"(r[1]), "=r"(r[2]), "=r"(r[3]) : "r"(addr));
}
__device__ __forceinline__ void mma_bf16(float4& d, const uint32_t a[4],
                                         uint32_t b0, uint32_t b1) {
    asm volatile(
        "mma.sync.aligned.m16n8k16.row.col.f32.bf16.bf16.f32 "
        "{%0,%1,%2,%3}, {%4,%5,%6,%7}, {%8,%9}, {%0,%1,%2,%3};"
        : "+f"(d.x), "+f"(d.y), "+f"(d.z), "+f"(d.w)
        : "r"(a[0]), "r"(a[1]), "r"(a[2]), "r"(a[3]), "r"(b0), "r"(b1));
}
__device__ __forceinline__ uint32_t bfpack(float a, float b) {
    __nv_bfloat162 h;
    h.x = __float2bfloat16(a); h.y = __float2bfloat16(b);
    return *(uint32_t*)&h;
}

// ---------------- K0: zero Z, wgv = w_mv @ w_g ------------------------------
__global__ void k0_prep(const float* __restrict__ wmv, const float* __restrict__ wg) {
    int t = blockIdx.x * blockDim.x + threadIdx.x;
    if (t < Bq * Nn) g_Z[t] = 0.0f;
    if (t < Cc * Cc) {
        int d = t >> 6, ci = t & 63;
        float s = 0.0f;
#pragma unroll
        for (int c = 0; c < 64; c++) s += wmv[d * 64 + c] * wg[c * 64 + ci];
        g_wgv[t] = s;
    }
}

// ---------------- K0w: split wmk into bf16 hi/lo ----------------------------
__global__ __launch_bounds__(256) void k0w_split(const float* __restrict__ wmk) {
    int i = blockIdx.x * 256 + threadIdx.x;
    float4 v = ((const float4*)wmk)[i];
    __nv_bfloat16 h0 = __float2bfloat16(v.x), h1 = __float2bfloat16(v.y);
    __nv_bfloat16 h2 = __float2bfloat16(v.z), h3 = __float2bfloat16(v.w);
    uint32_t hA = bfpack(v.x, v.y), hB = bfpack(v.z, v.w);
    uint32_t lA = bfpack(v.x - __bfloat162float(h0), v.y - __bfloat162float(h1));
    uint32_t lB = bfpack(v.z - __bfloat162float(h2), v.w - __bfloat162float(h3));
    ((uint2*)g_wmkH)[i] = make_uint2(hA, hB);
    ((uint2*)g_wmkL)[i] = make_uint2(lA, lB);
}

// ---------------- K1: channel GEMMs: phi (bf16 split), theta, gm ------------
__global__ __launch_bounds__(256) void k1_channel(
    const float* __restrict__ x, const float* __restrict__ wphi,
    const float* __restrict__ wtheta) {
    __shared__ __align__(16) float sX[64][68];
    __shared__ __align__(16) float sW[64][68];
    int b = blockIdx.x, n0 = blockIdx.y << 6;
    int t = threadIdx.x, ty = t >> 4, tx = t & 15;

#pragma unroll
    for (int i = 0; i < 16; i++) {
        int idx = t + (i << 8);
        int ci = idx >> 6, nn = idx & 63;
        sX[ci][nn] = x[((b << 6) + ci) * Nn + n0 + nn];
    }

    const float* Ws[3] = {wphi, wtheta, g_wgv};

    for (int p = 0; p < 3; p++) {
        __syncthreads();
#pragma unroll
        for (int i = 0; i < 16; i++) {
            int idx = t + (i << 8);
            int c = idx >> 6, ci = idx & 63;
            sW[ci][c] = Ws[p][idx];
        }
        __syncthreads();

        ull acc[4][2] = {};
#pragma unroll 8
        for (int ci = 0; ci < 64; ci++) {
            float4 av = *(const float4*)&sW[ci][ty << 2];
            ulonglong2 bv = *(const ulonglong2*)&sX[ci][tx << 2];
            ull a0 = pk2(av.x, av.x), a1 = pk2(av.y, av.y);
            ull a2 = pk2(av.z, av.z), a3 = pk2(av.w, av.w);
            fma2(acc[0][0], a0, bv.x); fma2(acc[0][1], a0, bv.y);
            fma2(acc[1][0], a1, bv.x); fma2(acc[1][1], a1, bv.y);
            fma2(acc[2][0], a2, bv.x); fma2(acc[2][1], a2, bv.y);
            fma2(acc[3][0], a3, bv.x); fma2(acc[3][1], a3, bv.y);
        }
        float v[4][4];
#pragma unroll
        for (int i = 0; i < 4; i++) {
            float2 v0 = upk2(acc[i][0]), v1 = upk2(acc[i][1]);
            v[i][0] = v0.x; v[i][1] = v0.y; v[i][2] = v1.x; v[i][3] = v1.y;
        }
        if (p == 0) {
#pragma unroll
            for (int i = 0; i < 4; i++) {
                int base = ((b << 6) + (ty << 2) + i) * Nn + n0 + (tx << 2);
                float lo0 = v[i][0], lo1 = v[i][1], lo2 = v[i][2], lo3 = v[i][3];
                uint32_t hA = bfpack(lo0, lo1), hB = bfpack(lo2, lo3);
                __nv_bfloat162* hp = (__nv_bfloat162*)&hA;
                __nv_bfloat162* hq = (__nv_bfloat162*)&hB;
                uint32_t lA = bfpack(lo0 - __bfloat162float(hp->x),
                                     lo1 - __bfloat162float(hp->y));
                uint32_t lB = bfpack(lo2 - __bfloat162float(hq->x),
                                     lo3 - __bfloat162float(hq->y));
                *(uint2*)&g_phiH[base] = make_uint2(hA, hB);
                *(uint2*)&g_phiL[base] = make_uint2(lA, lB);
            }
        } else {
            float* O = (p == 1 ? g_theta : g_gm) + (b << 6) * Nn + n0;
#pragma unroll
            for (int i = 0; i < 4; i++)
                *(float4*)&O[((ty << 2) + i) * Nn + (tx << 2)] =
                    make_float4(v[i][0], v[i][1], v[i][2], v[i][3]);
        }
    }
}

// ---------------- K2: P = phi @ wmk^T  (mma.sync bf16x3) --------------------
// grid (32 b, 8 ktile), block 256 = 8 warps. Warp tile: 16 c x 64 k. K=1024.
__global__ __launch_bounds__(256) void k2_P_mma(void) {
    extern __shared__ __align__(16) char sm2[];
    __nv_bfloat16* sAh = (__nv_bfloat16*)sm2;              // [64][72]
    __nv_bfloat16* sAl = (__nv_bfloat16*)(sm2 + 9216);     // [64][72]
    __nv_bfloat16* sBh = (__nv_bfloat16*)(sm2 + 18432);    // [128][72]
    __nv_bfloat16* sBl = (__nv_bfloat16*)(sm2 + 36864);    // [128][72]
    int b = blockIdx.x, k0 = blockIdx.y << 7;
    int t = threadIdx.x, w = t >> 5, lane = t & 31;
    int cgrp = w & 3, kgrp = w >> 2;

    const __nv_bfloat16* Ah = g_phiH + (size_t)(b << 6) * Nn;
    const __nv_bfloat16* Al = g_phiL + (size_t)(b << 6) * Nn;

    float4 acc[8] = {};
    int lr = lane & 15, lh = lane >> 4;
    int bq = lane >> 3, br = lane & 7;

    for (int mc = 0; mc < Nn; mc += 64) {
        __syncthreads();
#pragma unroll
        for (int i = 0; i < 2; i++) {
            int lin = t + (i << 8);
            int r = lin >> 3, j = lin & 7;
            *(uint4*)&sAh[r * 72 + j * 8] = *(const uint4*)&Ah[(size_t)r * Nn + mc + j * 8];
            *(uint4*)&sAl[r * 72 + j * 8] = *(const uint4*)&Al[(size_t)r * Nn + mc + j * 8];
        }
#pragma unroll
        for (int i = 0; i < 4; i++) {
            int lin = t + (i << 8);
            int r = lin >> 3, j = lin & 7;
            *(uint4*)&sBh[r * 72 + j * 8] =
                *(const uint4*)&g_wmkH[(size_t)(k0 + r) * Nn + mc + j * 8];
            *(uint4*)&sBl[r * 72 + j * 8] =
                *(const uint4*)&g_wmkL[(size_t)(k0 + r) * Nn + mc + j * 8];
        }
        __syncthreads();
#pragma unroll
        for (int kk = 0; kk < 4; kk++) {
            uint32_t ah[4], al[4];
            ldsm_x4(smem_u32(&sAh[(cgrp * 16 + lr) * 72 + kk * 16 + lh * 8]), ah);
            ldsm_x4(smem_u32(&sAl[(cgrp * 16 + lr) * 72 + kk * 16 + lh * 8]), al);
#pragma unroll
            for (int j = 0; j < 4; j++) {
                int rowb = (kgrp << 6) + (j << 4) + ((bq >> 1) << 3) + br;
                int colb = (kk << 4) + ((bq & 1) << 3);
                uint32_t bh[4], bl[4];
                ldsm_x4(smem_u32(&sBh[rowb * 72 + colb]), bh);
                mma_bf16(acc[j * 2], ah, bh[0], bh[1]);
                mma_bf16(acc[j * 2 + 1], ah, bh[2], bh[3]);
                mma_bf16(acc[j * 2], al, bh[0], bh[1]);
                mma_bf16(acc[j * 2 + 1], al, bh[2], bh[3]);
                ldsm_x4(smem_u32(&sBl[rowb * 72 + colb]), bl);
                mma_bf16(acc[j * 2], ah, bl[0], bl[1]);
                mma_bf16(acc[j * 2 + 1], ah, bl[2], bl[3]);
            }
        }
    }
    int m = (cgrp << 4) + (lane >> 2);
    float* Pb = g_P + ((size_t)(b << 6) + m) * Nn + k0;
#pragma unroll
    for (int f = 0; f < 8; f++) {
        int n = (kgrp << 6) + ((f >> 1) << 4) + ((f & 1) << 3) + ((lane & 3) << 1);
        *(float2*)&Pb[n] = make_float2(acc[f].x, acc[f].y);
        *(float2*)&Pb[8 * Nn + n] = make_float2(acc[f].z, acc[f].w);
    }
}

// ---------------- K3: E_t[k][n] = exp(sum_c theta[c][n] P[c][k]), Z sums ----
__global__ __launch_bounds__(256, 2) void k3_att(void) {
    __shared__ __align__(16) float sP[32][132];
    __shared__ __align__(16) float sT[32][132];
    __shared__ float red[128][17];
    int b = blockIdx.z, n0 = blockIdx.y << 7, k0 = blockIdx.x << 7;
    int t = threadIdx.x, ty = t >> 4, tx = t & 15;
    const float* th = g_theta + (b << 6) * Nn;
    const float* Pp = g_P + (b << 6) * Nn;

    ull acc[8][4] = {};
    for (int c0 = 0; c0 < 64; c0 += 32) {
        __syncthreads();
#pragma unroll
        for (int i = 0; i < 4; i++) {
            int idx = t + (i << 8);
            int r = idx >> 5, c4 = idx & 31;
            *(float4*)&sT[r][c4 << 2] = *(const float4*)&th[(c0 + r) * Nn + n0 + (c4 << 2)];
            *(float4*)&sP[r][c4 << 2] = *(const float4*)&Pp[(c0 + r) * Nn + k0 + (c4 << 2)];
        }
        __syncthreads();
#pragma unroll
        for (int cc = 0; cc < 32; cc++) {
            float4 a0 = *(const float4*)&sP[cc][ty << 3];
            float4 a1 = *(const float4*)&sP[cc][(ty << 3) + 4];
            ulonglong2 b0 = *(const ulonglong2*)&sT[cc][tx << 2];
            ulonglong2 b1 = *(const ulonglong2*)&sT[cc][64 + (tx << 2)];
            float kv[8] = {a0.x, a0.y, a0.z, a0.w, a1.x, a1.y, a1.z, a1.w};
            FMA_ROW8(acc, kv, b0, b1);
        }
    }
    float* Et = g_E + (size_t)(b * Nn + k0 + (ty << 3)) * Nn + n0;
#pragma unroll
    for (int i = 0; i < 8; i++) {
        float2 v0 = upk2(acc[i][0]), v1 = upk2(acc[i][1]);
        float2 v2 = upk2(acc[i][2]), v3 = upk2(acc[i][3]);
        float e0 = __expf(v0.x), e1 = __expf(v0.y);
        float e2 = __expf(v1.x), e3 = __expf(v1.y);
        float e4 = __expf(v2.x), e5 = __expf(v2.y);
        float e6 = __expf(v3.x), e7 = __expf(v3.y);
        *(float4*)&Et[i * Nn + (tx << 2)] = make_float4(e0, e1, e2, e3);
        *(float4*)&Et[i * Nn + 64 + (tx << 2)] = make_float4(e4, e5, e6, e7);
        red[(ty << 3) + i][tx] = e0 + e1 + e2 + e3 + e4 + e5 + e6 + e7;
    }
    __syncthreads();
    if (t < 128) {
        float s = 0.0f;
#pragma unroll
        for (int j = 0; j < 16; j++) s += red[t][j];
        atomicAdd(&g_Z[b * Nn + k0 + t], s);
    }
}

// ---------------- K5: gzT[o][m] = (sum_c wmask[o][c] gm[c][m]) / Z[m] -------
__global__ __launch_bounds__(256) void k5_gmz(const float* __restrict__ wmask) {
    __shared__ __align__(16) float smG[64][68];
    __shared__ __align__(16) float smW[64][68];
    __shared__ float sz[64];
    int b = blockIdx.x, m0 = blockIdx.y << 6;
    int t = threadIdx.x;
    const float* gm = g_gm + (b << 6) * Nn;
#pragma unroll
    for (int i = 0; i < 4; i++) {
        int idx = t + (i << 8);
        int r = idx >> 4, c4 = idx & 15;
        *(float4*)&smG[r][c4 << 2] = *(const float4*)&gm[r * Nn + m0 + (c4 << 2)];
        *(float4*)&smW[r][c4 << 2] = *(const float4*)&wmask[r * 64 + (c4 << 2)];
    }
    if (t < 64) sz[t] = 1.0f / g_Z[b * Nn + m0 + t];
    __syncthreads();
    int m = t & 63, og = t >> 6;
    float inv = sz[m];
#pragma unroll
    for (int q = 0; q < 16; q++) {
        int o = (og << 4) + q;
        float s = 0.0f;
#pragma unroll
        for (int c = 0; c < 64; c++) s += smW[o][c] * smG[c][m];
        g_gzT[((size_t)(b << 6) + o) * Nn + m0 + m] = s * inv;
    }
}

// ---------------- K4: out = gzT^T applied: out[o][n] = sum_m gzT[o][m] E[m][n] + x
// grid (32 b, 8 ntile), block 256 = 8 warps. Warp tile: 16 o x 64 n. K=1024(m).
__global__ __launch_bounds__(256) void k4_out_mma(
    const float* __restrict__ x, float* __restrict__ out) {
    extern __shared__ __align__(16) char sm4[];
    __nv_bfloat16* sAh = (__nv_bfloat16*)sm4;              // [64 o][72 m]
    __nv_bfloat16* sAl = (__nv_bfloat16*)(sm4 + 9216);
    __nv_bfloat16* sBh = (__nv_bfloat16*)(sm4 + 18432);    // [64 m][136 n]
    __nv_bfloat16* sBl = (__nv_bfloat16*)(sm4 + 35840);
    int b = blockIdx.x, n0 = blockIdx.y << 7;
    int t = threadIdx.x, w = t >> 5, lane = t & 31;
    int ogrp = w & 3, ngrp = w >> 2;

    float4 acc[8] = {};
    int lr = lane & 15, lh = lane >> 4;
    int bq = lane >> 3, br = lane & 7;

    for (int mc = 0; mc < Nn; mc += 64) {
        __syncthreads();
        // stage A = gzT [o][m] fp32 -> hi/lo bf16
#pragma unroll
        for (int i = 0; i < 4; i++) {
            int lin = t + (i << 8);
            int r = lin >> 4, j = lin & 15;
            float4 v = *(const float4*)&g_gzT[((size_t)(b << 6) + r) * Nn + mc + (j << 2)];
            uint32_t hA = bfpack(v.x, v.y), hB = bfpack(v.z, v.w);
            __nv_bfloat162* hp = (__nv_bfloat162*)&hA;
            __nv_bfloat162* hq = (__nv_bfloat162*)&hB;
            uint32_t lA = bfpack(v.x - __bfloat162float(hp->x),
                                 v.y - __bfloat162float(hp->y));
            uint32_t lB = bfpack(v.z - __bfloat162float(hq->x),
                                 v.w - __bfloat162float(hq->y));
            *(uint2*)&sAh[r * 72 + (j << 2)] = make_uint2(hA, hB);
            *(uint2*)&sAl[r * 72 + (j << 2)] = make_uint2(lA, lB);
        }
        // stage B = E [m][n] fp32 -> hi/lo bf16
#pragma unroll
        for (int i = 0; i < 8; i++) {
            int lin = t + (i << 8);
            int r = lin >> 5, j = lin & 31;
            float4 v = *(const float4*)&g_E[((size_t)b * Nn + mc + r) * Nn + n0 + (j << 2)];
            uint32_t hA = bfpack(v.x, v.y), hB = bfpack(v.z, v.w);
            __nv_bfloat162* hp = (__nv_bfloat162*)&hA;
            __nv_bfloat162* hq = (__nv_bfloat162*)&hB;
            uint32_t lA = bfpack(v.x - __bfloat162float(hp->x),
                                 v.y - __bfloat162float(hp->y));
            uint32_t lB = bfpack(v.z - __bfloat162float(hq->x),
                                 v.w - __bfloat162float(hq->y));
            *(uint2*)&sBh[r * 136 + (j << 2)] = make_uint2(hA, hB);
            *(uint2*)&sBl[r * 136 + (j << 2)] = make_uint2(lA, lB);
        }
        __syncthreads();
#pragma unroll
        for (int kk = 0; kk < 4; kk++) {
            uint32_t ah[4], al[4];
            ldsm_x4(smem_u32(&sAh[(ogrp * 16 + lr) * 72 + kk * 16 + lh * 8]), ah);
            ldsm_x4(smem_u32(&sAl[(ogrp * 16 + lr) * 72 + kk * 16 + lh * 8]), al);
#pragma unroll
            for (int j = 0; j < 4; j++) {
                // B tile rows = m, cols = n; ldmatrix.trans
                int rowm = (kk << 4) + ((bq & 1) << 3) + br;
                int coln = (ngrp << 6) + (j << 4) + ((bq >> 1) << 3);
                uint32_t bh[4], bl[4];
                ldsm_x4t(smem_u32(&sBh[rowm * 136 + coln]), bh);
                mma_bf16(acc[j * 2], ah, bh[0], bh[1]);
                mma_bf16(acc[j * 2 + 1], ah, bh[2], bh[3]);
                mma_bf16(acc[j * 2], al, bh[0], bh[1]);
                mma_bf16(acc[j * 2 + 1], al, bh[2], bh[3]);
                ldsm_x4t(smem_u32(&sBl[rowm * 136 + coln]), bl);
                mma_bf16(acc[j * 2], ah, bl[0], bl[1]);
                mma_bf16(acc[j * 2 + 1], ah, bl[2], bl[3]);
            }
        }
    }
    int o = (ogrp << 4) + (lane >> 2);
#pragma unroll
    for (int f = 0; f < 8; f++) {
        int n = n0 + (ngrp << 6) + ((f >> 1) << 4) + ((f & 1) << 3) + ((lane & 3) << 1);
        size_t off = ((size_t)(b << 6) + o) * Nn + n;
        float2 xv = *(const float2*)&x[off];
        *(float2*)&out[off] = make_float2(acc[f].x + xv.x, acc[f].y + xv.y);
        size_t off2 = off + (size_t)8 * Nn;
        float2 xv2 = *(const float2*)&x[off2];
        *(float2*)&out[off2] = make_float2(acc[f].z + xv2.x, acc[f].w + xv2.y);
    }
}

// ---------------- launch ----------------------------------------------------
extern "C" void kernel_launch(void* const* d_in, const int* in_sizes, int n_in,
                              void* d_out, int out_size) {
    const float* x      = (const float*)d_in[0];
    const float* wphi   = (const float*)d_in[1];
    const float* wtheta = (const float*)d_in[2];
    const float* wg     = (const float*)d_in[3];
    const float* wmask  = (const float*)d_in[4];
    const float* wmv    = (const float*)d_in[5];
    const float* wmk    = (const float*)d_in[6];
    float* out = (float*)d_out;

    cudaFuncSetAttribute(k2_P_mma, cudaFuncAttributeMaxDynamicSharedMemorySize, 55296);
    cudaFuncSetAttribute(k4_out_mma, cudaFuncAttributeMaxDynamicSharedMemorySize, 53248);

    k0_prep<<<128, 256>>>(wmv, wg);
    k0w_split<<<1024, 256>>>(wmk);
    k1_channel<<<dim3(32, 16), 256>>>(x, wphi, wtheta);
    k2_P_mma<<<dim3(32, 8), 256, 55296>>>();
    k3_att<<<dim3(8, 8, 32), 256>>>();
    k5_gmz<<<dim3(32, 16), 256>>>(wmask);
    k4_out_mma<<<dim3(32, 8), 256, 53248>>>(x, out);
}

// round 6
// speedup vs baseline: 1.4823x; 1.0584x over previous
#include <cuda_runtime.h>
#include <cuda_bf16.h>
#include <cstdint>

#define Bq 32
#define Cc 64
#define Nn 1024

typedef unsigned long long ull;

// ---------------- scratch (device globals) ----------------------------------
__device__ __nv_bfloat16 g_phiH[Bq * Cc * Nn];  // [b][c][m] phi hi
__device__ __nv_bfloat16 g_phiL[Bq * Cc * Nn];  // [b][c][m] phi lo
__device__ __nv_bfloat16 g_wmkH[Nn * Nn];       // [k][m] wmk hi
__device__ __nv_bfloat16 g_wmkL[Nn * Nn];       // [k][m] wmk lo
__device__ float g_theta[Bq * Cc * Nn];   // [b][c][n]
__device__ float g_gm[Bq * Cc * Nn];      // [b][c][n]
__device__ float g_P[Bq * Cc * Nn];       // [b][c][k]
__device__ __nv_bfloat16 g_EH[(size_t)Bq * Nn * Nn];  // [b][k][n] exp hi (64MB)
__device__ __nv_bfloat16 g_EL[(size_t)Bq * Nn * Nn];  // [b][k][n] exp lo (64MB)
__device__ float g_Z[Bq * Nn];
__device__ float g_wgv[Cc * Cc];          // w_mv @ w_g
__device__ float g_gzT[Bq * Cc * Nn];     // [b][o][m]  (w_mask@gm)/Z

// ---------------- f32x2 helpers ---------------------------------------------
__device__ __forceinline__ ull pk2(float lo, float hi) {
    ull r;
    asm("mov.b64 %0, {%1, %2};" : "=l"(r) : "f"(lo), "f"(hi));
    return r;
}
__device__ __forceinline__ void fma2(ull& d, ull a, ull b) {
    asm("fma.rn.f32x2 %0, %1, %2, %0;" : "+l"(d) : "l"(a), "l"(b));
}
__device__ __forceinline__ float2 upk2(ull v) {
    float2 r;
    asm("mov.b64 {%0, %1}, %2;" : "=f"(r.x), "=f"(r.y) : "l"(v));
    return r;
}

// ---------------- mma.sync helpers ------------------------------------------
__device__ __forceinline__ uint32_t smem_u32(const void* p) {
    uint32_t a;
    asm("{ .reg .u64 t; cvta.to.shared.u64 t, %1; cvt.u32.u64 %0, t; }"
        : "=r"(a) : "l"(p));
    return a;
}
__device__ __forceinline__ void ldsm_x4(uint32_t addr, uint32_t r[4]) {
    asm volatile("ldmatrix.sync.aligned.m8n8.x4.shared.b16 {%0,%1,%2,%3}, [%4];"
                 : "=r"(r[0]), "=r"(r[1]), "=r"(r[2]), "=r"(r[3]) : "r"(addr));
}
__device__ __forceinline__ void ldsm_x4t(uint32_t addr, uint32_t r[4]) {
    asm volatile("ldmatrix.sync.aligned.m8n8.x4.trans.shared.b16 {%0,%1,%2,%3}, [%4];"
                 : "=r"(r[0]), "=r"(r[1]), "=r"(r[2]), "=r"(r[3]) : "r"(addr));
}
__device__ __forceinline__ void mma_bf16(float4& d, const uint32_t a[4],
                                         uint32_t b0, uint32_t b1) {
    asm volatile(
        "mma.sync.aligned.m16n8k16.row.col.f32.bf16.bf16.f32 "
        "{%0,%1,%2,%3}, {%4,%5,%6,%7}, {%8,%9}, {%0,%1,%2,%3};"
        : "+f"(d.x), "+f"(d.y), "+f"(d.z), "+f"(d.w)
        : "r"(a[0]), "r"(a[1]), "r"(a[2]), "r"(a[3]), "r"(b0), "r"(b1));
}
__device__ __forceinline__ uint32_t bfpack(float a, float b) {
    __nv_bfloat162 h;
    h.x = __float2bfloat16(a); h.y = __float2bfloat16(b);
    return *(uint32_t*)&h;
}
// split float4 into hi/lo packed pairs
__device__ __forceinline__ void split4(float4 v, uint2& hi, uint2& lo) {
    uint32_t hA = bfpack(v.x, v.y), hB = bfpack(v.z, v.w);
    __nv_bfloat162* hp = (__nv_bfloat162*)&hA;
    __nv_bfloat162* hq = (__nv_bfloat162*)&hB;
    uint32_t lA = bfpack(v.x - __bfloat162float(hp->x), v.y - __bfloat162float(hp->y));
    uint32_t lB = bfpack(v.z - __bfloat162float(hq->x), v.w - __bfloat162float(hq->y));
    hi = make_uint2(hA, hB); lo = make_uint2(lA, lB);
}

// ---------------- K0: zero Z, wgv = w_mv @ w_g ------------------------------
__global__ void k0_prep(const float* __restrict__ wmv, const float* __restrict__ wg) {
    int t = blockIdx.x * blockDim.x + threadIdx.x;
    if (t < Bq * Nn) g_Z[t] = 0.0f;
    if (t < Cc * Cc) {
        int d = t >> 6, ci = t & 63;
        float s = 0.0f;
#pragma unroll
        for (int c = 0; c < 64; c++) s += wmv[d * 64 + c] * wg[c * 64 + ci];
        g_wgv[t] = s;
    }
}

// ---------------- K0w: split wmk into bf16 hi/lo ----------------------------
__global__ __launch_bounds__(256) void k0w_split(const float* __restrict__ wmk) {
    int i = blockIdx.x * 256 + threadIdx.x;
    float4 v = ((const float4*)wmk)[i];
    uint2 hi, lo;
    split4(v, hi, lo);
    ((uint2*)g_wmkH)[i] = hi;
    ((uint2*)g_wmkL)[i] = lo;
}

// ---------------- K1: channel GEMMs: phi (bf16 split), theta, gm ------------
__global__ __launch_bounds__(256) void k1_channel(
    const float* __restrict__ x, const float* __restrict__ wphi,
    const float* __restrict__ wtheta) {
    __shared__ __align__(16) float sX[64][68];
    __shared__ __align__(16) float sW[64][68];
    int b = blockIdx.x, n0 = blockIdx.y << 6;
    int t = threadIdx.x, ty = t >> 4, tx = t & 15;

#pragma unroll
    for (int i = 0; i < 16; i++) {
        int idx = t + (i << 8);
        int ci = idx >> 6, nn = idx & 63;
        sX[ci][nn] = x[((b << 6) + ci) * Nn + n0 + nn];
    }

    const float* Ws[3] = {wphi, wtheta, g_wgv};

    for (int p = 0; p < 3; p++) {
        __syncthreads();
#pragma unroll
        for (int i = 0; i < 16; i++) {
            int idx = t + (i << 8);
            int c = idx >> 6, ci = idx & 63;
            sW[ci][c] = Ws[p][idx];
        }
        __syncthreads();

        ull acc[4][2] = {};
#pragma unroll 8
        for (int ci = 0; ci < 64; ci++) {
            float4 av = *(const float4*)&sW[ci][ty << 2];
            ulonglong2 bv = *(const ulonglong2*)&sX[ci][tx << 2];
            ull a0 = pk2(av.x, av.x), a1 = pk2(av.y, av.y);
            ull a2 = pk2(av.z, av.z), a3 = pk2(av.w, av.w);
            fma2(acc[0][0], a0, bv.x); fma2(acc[0][1], a0, bv.y);
            fma2(acc[1][0], a1, bv.x); fma2(acc[1][1], a1, bv.y);
            fma2(acc[2][0], a2, bv.x); fma2(acc[2][1], a2, bv.y);
            fma2(acc[3][0], a3, bv.x); fma2(acc[3][1], a3, bv.y);
        }
        float v[4][4];
#pragma unroll
        for (int i = 0; i < 4; i++) {
            float2 v0 = upk2(acc[i][0]), v1 = upk2(acc[i][1]);
            v[i][0] = v0.x; v[i][1] = v0.y; v[i][2] = v1.x; v[i][3] = v1.y;
        }
        if (p == 0) {
#pragma unroll
            for (int i = 0; i < 4; i++) {
                int base = ((b << 6) + (ty << 2) + i) * Nn + n0 + (tx << 2);
                float4 pv = make_float4(v[i][0], v[i][1], v[i][2], v[i][3]);
                uint2 hi, lo;
                split4(pv, hi, lo);
                *(uint2*)&g_phiH[base] = hi;
                *(uint2*)&g_phiL[base] = lo;
            }
        } else {
            float* O = (p == 1 ? g_theta : g_gm) + (b << 6) * Nn + n0;
#pragma unroll
            for (int i = 0; i < 4; i++)
                *(float4*)&O[((ty << 2) + i) * Nn + (tx << 2)] =
                    make_float4(v[i][0], v[i][1], v[i][2], v[i][3]);
        }
    }
}

// ---------------- K2: P = phi @ wmk^T  (mma.sync bf16x3) --------------------
// grid (32 b, 8 ktile), block 256 = 8 warps. Warp tile: 16 c x 64 k. K=1024.
__global__ __launch_bounds__(256, 2) void k2_P_mma(void) {
    extern __shared__ __align__(16) char sm2[];
    __nv_bfloat16* sAh = (__nv_bfloat16*)sm2;              // [64][72]
    __nv_bfloat16* sAl = (__nv_bfloat16*)(sm2 + 9216);     // [64][72]
    __nv_bfloat16* sBh = (__nv_bfloat16*)(sm2 + 18432);    // [128][72]
    __nv_bfloat16* sBl = (__nv_bfloat16*)(sm2 + 36864);    // [128][72]
    int b = blockIdx.x, k0 = blockIdx.y << 7;
    int t = threadIdx.x, w = t >> 5, lane = t & 31;
    int cgrp = w & 3, kgrp = w >> 2;

    const __nv_bfloat16* Ah = g_phiH + (size_t)(b << 6) * Nn;
    const __nv_bfloat16* Al = g_phiL + (size_t)(b << 6) * Nn;

    float4 acc[8] = {};
    int lr = lane & 15, lh = lane >> 4;
    int bq = lane >> 3, br = lane & 7;

    for (int mc = 0; mc < Nn; mc += 64) {
        __syncthreads();
#pragma unroll
        for (int i = 0; i < 2; i++) {
            int lin = t + (i << 8);
            int r = lin >> 3, j = lin & 7;
            *(uint4*)&sAh[r * 72 + j * 8] = *(const uint4*)&Ah[(size_t)r * Nn + mc + j * 8];
            *(uint4*)&sAl[r * 72 + j * 8] = *(const uint4*)&Al[(size_t)r * Nn + mc + j * 8];
        }
#pragma unroll
        for (int i = 0; i < 4; i++) {
            int lin = t + (i << 8);
            int r = lin >> 3, j = lin & 7;
            *(uint4*)&sBh[r * 72 + j * 8] =
                *(const uint4*)&g_wmkH[(size_t)(k0 + r) * Nn + mc + j * 8];
            *(uint4*)&sBl[r * 72 + j * 8] =
                *(const uint4*)&g_wmkL[(size_t)(k0 + r) * Nn + mc + j * 8];
        }
        __syncthreads();
#pragma unroll
        for (int kk = 0; kk < 4; kk++) {
            uint32_t ah[4], al[4];
            ldsm_x4(smem_u32(&sAh[(cgrp * 16 + lr) * 72 + kk * 16 + lh * 8]), ah);
            ldsm_x4(smem_u32(&sAl[(cgrp * 16 + lr) * 72 + kk * 16 + lh * 8]), al);
#pragma unroll
            for (int j = 0; j < 4; j++) {
                int rowb = (kgrp << 6) + (j << 4) + ((bq >> 1) << 3) + br;
                int colb = (kk << 4) + ((bq & 1) << 3);
                uint32_t bh[4], bl[4];
                ldsm_x4(smem_u32(&sBh[rowb * 72 + colb]), bh);
                mma_bf16(acc[j * 2], ah, bh[0], bh[1]);
                mma_bf16(acc[j * 2 + 1], ah, bh[2], bh[3]);
                mma_bf16(acc[j * 2], al, bh[0], bh[1]);
                mma_bf16(acc[j * 2 + 1], al, bh[2], bh[3]);
                ldsm_x4(smem_u32(&sBl[rowb * 72 + colb]), bl);
                mma_bf16(acc[j * 2], ah, bl[0], bl[1]);
                mma_bf16(acc[j * 2 + 1], ah, bl[2], bl[3]);
            }
        }
    }
    int m = (cgrp << 4) + (lane >> 2);
    float* Pb = g_P + ((size_t)(b << 6) + m) * Nn + k0;
#pragma unroll
    for (int f = 0; f < 8; f++) {
        int n = (kgrp << 6) + ((f >> 1) << 4) + ((f & 1) << 3) + ((lane & 3) << 1);
        *(float2*)&Pb[n] = make_float2(acc[f].x, acc[f].y);
        *(float2*)&Pb[8 * Nn + n] = make_float2(acc[f].z, acc[f].w);
    }
}

// ---------------- K3: Et = exp(P^T theta), bf16 hi/lo out, Z sums -----------
// grid (8 ktile, 8 ntile, 32 b), block 256 = 8 warps (4 k-groups x 2 n-groups)
// CTA tile 128k x 128n, reduction c = 64. A = P[c][k] (trans), B = theta[c][n] (trans).
__global__ __launch_bounds__(256, 2) void k3_att_mma(void) {
    extern __shared__ __align__(16) char sm3[];
    __nv_bfloat16* sPh = (__nv_bfloat16*)sm3;              // [64][136]
    __nv_bfloat16* sPl = (__nv_bfloat16*)(sm3 + 17408);
    __nv_bfloat16* sTh = (__nv_bfloat16*)(sm3 + 34816);
    __nv_bfloat16* sTl = (__nv_bfloat16*)(sm3 + 52224);
    int b = blockIdx.z, k0 = blockIdx.x << 7, n0 = blockIdx.y << 7;
    int t = threadIdx.x, w = t >> 5, lane = t & 31;
    int kw = w & 3, nw = w >> 2;
    const float* Pp = g_P + (size_t)(b << 6) * Nn;
    const float* th = g_theta + (size_t)(b << 6) * Nn;

    // stage + split: P[c][k0..+128], theta[c][n0..+128]
#pragma unroll
    for (int i = 0; i < 8; i++) {
        int lin = t + (i << 8);
        int r = lin >> 5, j = lin & 31;
        float4 v = *(const float4*)&Pp[(size_t)r * Nn + k0 + (j << 2)];
        uint2 hi, lo;
        split4(v, hi, lo);
        *(uint2*)&sPh[r * 136 + (j << 2)] = hi;
        *(uint2*)&sPl[r * 136 + (j << 2)] = lo;
        float4 u = *(const float4*)&th[(size_t)r * Nn + n0 + (j << 2)];
        split4(u, hi, lo);
        *(uint2*)&sTh[r * 136 + (j << 2)] = hi;
        *(uint2*)&sTl[r * 136 + (j << 2)] = lo;
    }
    __syncthreads();

    float4 acc[2][8] = {};
    int bq = lane >> 3, br = lane & 7;
#pragma unroll
    for (int kk = 0; kk < 4; kk++) {
        int c0 = kk << 4;
        uint32_t ah[2][4], al[2][4];
#pragma unroll
        for (int mt = 0; mt < 2; mt++) {
            int m0 = (kw << 5) + (mt << 4);
            int rowc = c0 + ((bq >> 1) << 3) + br;
            int colm = m0 + ((bq & 1) << 3);
            ldsm_x4t(smem_u32(&sPh[rowc * 136 + colm]), ah[mt]);
            ldsm_x4t(smem_u32(&sPl[rowc * 136 + colm]), al[mt]);
        }
#pragma unroll
        for (int j = 0; j < 4; j++) {
            int rowc = c0 + ((bq & 1) << 3) + br;
            int coln = (nw << 6) + (j << 4) + ((bq >> 1) << 3);
            uint32_t bh[4], bl[4];
            ldsm_x4t(smem_u32(&sTh[rowc * 136 + coln]), bh);
            ldsm_x4t(smem_u32(&sTl[rowc * 136 + coln]), bl);
#pragma unroll
            for (int mt = 0; mt < 2; mt++) {
                mma_bf16(acc[mt][j * 2], ah[mt], bh[0], bh[1]);
                mma_bf16(acc[mt][j * 2 + 1], ah[mt], bh[2], bh[3]);
                mma_bf16(acc[mt][j * 2], al[mt], bh[0], bh[1]);
                mma_bf16(acc[mt][j * 2 + 1], al[mt], bh[2], bh[3]);
                mma_bf16(acc[mt][j * 2], ah[mt], bl[0], bl[1]);
                mma_bf16(acc[mt][j * 2 + 1], ah[mt], bl[2], bl[3]);
            }
        }
    }

    // exp + Z partials + fragment -> smem (reuse buffers as sEH/sEL [128][136])
    __syncthreads();
    __nv_bfloat16* sEH = (__nv_bfloat16*)sm3;
    __nv_bfloat16* sEL = (__nv_bfloat16*)(sm3 + 34816);
#pragma unroll
    for (int mt = 0; mt < 2; mt++) {
        int krow = (kw << 5) + (mt << 4) + (lane >> 2);
        float sA = 0.f, sB = 0.f;
#pragma unroll
        for (int j = 0; j < 8; j++) {
            int nc = (nw << 6) + (j << 3) + ((lane & 3) << 1);
            float ex = __expf(acc[mt][j].x), ey = __expf(acc[mt][j].y);
            float ez = __expf(acc[mt][j].z), ew = __expf(acc[mt][j].w);
            sA += ex + ey; sB += ez + ew;
            uint32_t h0 = bfpack(ex, ey);
            __nv_bfloat162* hp = (__nv_bfloat162*)&h0;
            uint32_t l0 = bfpack(ex - __bfloat162float(hp->x),
                                 ey - __bfloat162float(hp->y));
            *(uint32_t*)&sEH[krow * 136 + nc] = h0;
            *(uint32_t*)&sEL[krow * 136 + nc] = l0;
            uint32_t h1 = bfpack(ez, ew);
            __nv_bfloat162* hq = (__nv_bfloat162*)&h1;
            uint32_t l1 = bfpack(ez - __bfloat162float(hq->x),
                                 ew - __bfloat162float(hq->y));
            *(uint32_t*)&sEH[(krow + 8) * 136 + nc] = h1;
            *(uint32_t*)&sEL[(krow + 8) * 136 + nc] = l1;
        }
        sA += __shfl_xor_sync(0xffffffffu, sA, 1);
        sA += __shfl_xor_sync(0xffffffffu, sA, 2);
        sB += __shfl_xor_sync(0xffffffffu, sB, 1);
        sB += __shfl_xor_sync(0xffffffffu, sB, 2);
        if ((lane & 3) == 0) {
            atomicAdd(&g_Z[b * Nn + k0 + krow], sA);
            atomicAdd(&g_Z[b * Nn + k0 + krow + 8], sB);
        }
    }
    __syncthreads();
    // coalesced copy out: 128 rows x 128 bf16
#pragma unroll
    for (int i = 0; i < 8; i++) {
        int lin = t + (i << 8);
        int r = lin >> 4, q = lin & 15;
        size_t off = ((size_t)(b * Nn + k0 + r)) * Nn + n0 + (q << 3);
        *(uint4*)&g_EH[off] = *(uint4*)&sEH[r * 136 + (q << 3)];
        *(uint4*)&g_EL[off] = *(uint4*)&sEL[r * 136 + (q << 3)];
    }
}

// ---------------- K5: gzT[o][m] = (sum_c wmask[o][c] gm[c][m]) / Z[m] -------
__global__ __launch_bounds__(256) void k5_gmz(const float* __restrict__ wmask) {
    __shared__ __align__(16) float smG[64][68];
    __shared__ __align__(16) float smW[64][68];
    __shared__ float sz[64];
    int b = blockIdx.x, m0 = blockIdx.y << 6;
    int t = threadIdx.x;
    const float* gm = g_gm + (b << 6) * Nn;
#pragma unroll
    for (int i = 0; i < 4; i++) {
        int idx = t + (i << 8);
        int r = idx >> 4, c4 = idx & 15;
        *(float4*)&smG[r][c4 << 2] = *(const float4*)&gm[r * Nn + m0 + (c4 << 2)];
        *(float4*)&smW[r][c4 << 2] = *(const float4*)&wmask[r * 64 + (c4 << 2)];
    }
    if (t < 64) sz[t] = 1.0f / g_Z[b * Nn + m0 + t];
    __syncthreads();
    int m = t & 63, og = t >> 6;
    float inv = sz[m];
#pragma unroll
    for (int q = 0; q < 16; q++) {
        int o = (og << 4) + q;
        float s = 0.0f;
#pragma unroll
        for (int c = 0; c < 64; c++) s += smW[o][c] * smG[c][m];
        g_gzT[((size_t)(b << 6) + o) * Nn + m0 + m] = s * inv;
    }
}

// ---------------- K4: out[o][n] = sum_m gzT[o][m] E[m][n] + x ---------------
// grid (32 b, 8 ntile), block 256 = 8 warps. Warp tile: 16 o x 64 n. K=1024(m).
__global__ __launch_bounds__(256) void k4_out_mma(
    const float* __restrict__ x, float* __restrict__ out) {
    extern __shared__ __align__(16) char sm4[];
    __nv_bfloat16* sAh = (__nv_bfloat16*)sm4;              // [64 o][72 m]
    __nv_bfloat16* sAl = (__nv_bfloat16*)(sm4 + 9216);
    __nv_bfloat16* sBh = (__nv_bfloat16*)(sm4 + 18432);    // [64 m][136 n]
    __nv_bfloat16* sBl = (__nv_bfloat16*)(sm4 + 35840);
    int b = blockIdx.x, n0 = blockIdx.y << 7;
    int t = threadIdx.x, w = t >> 5, lane = t & 31;
    int ogrp = w & 3, ngrp = w >> 2;

    float4 acc[8] = {};
    int lr = lane & 15, lh = lane >> 4;
    int bq = lane >> 3, br = lane & 7;

    for (int mc = 0; mc < Nn; mc += 64) {
        __syncthreads();
        // stage A = gzT [o][m] fp32 -> hi/lo bf16
#pragma unroll
        for (int i = 0; i < 4; i++) {
            int lin = t + (i << 8);
            int r = lin >> 4, j = lin & 15;
            float4 v = *(const float4*)&g_gzT[((size_t)(b << 6) + r) * Nn + mc + (j << 2)];
            uint2 hi, lo;
            split4(v, hi, lo);
            *(uint2*)&sAh[r * 72 + (j << 2)] = hi;
            *(uint2*)&sAl[r * 72 + (j << 2)] = lo;
        }
        // stage B = EH/EL bf16, raw copies
#pragma unroll
        for (int i = 0; i < 4; i++) {
            int lin = t + (i << 8);
            int r = lin >> 4, q = lin & 15;
            size_t off = ((size_t)(b * Nn) + mc + r) * Nn + n0 + (q << 3);
            *(uint4*)&sBh[r * 136 + (q << 3)] = *(const uint4*)&g_EH[off];
            *(uint4*)&sBl[r * 136 + (q << 3)] = *(const uint4*)&g_EL[off];
        }
        __syncthreads();
#pragma unroll
        for (int kk = 0; kk < 4; kk++) {
            uint32_t ah[4], al[4];
            ldsm_x4(smem_u32(&sAh[(ogrp * 16 + lr) * 72 + kk * 16 + lh * 8]), ah);
            ldsm_x4(smem_u32(&sAl[(ogrp * 16 + lr) * 72 + kk * 16 + lh * 8]), al);
#pragma unroll
            for (int j = 0; j < 4; j++) {
                int rowm = (kk << 4) + ((bq & 1) << 3) + br;
                int coln = (ngrp << 6) + (j << 4) + ((bq >> 1) << 3);
                uint32_t bh[4], bl[4];
                ldsm_x4t(smem_u32(&sBh[rowm * 136 + coln]), bh);
                mma_bf16(acc[j * 2], ah, bh[0], bh[1]);
                mma_bf16(acc[j * 2 + 1], ah, bh[2], bh[3]);
                mma_bf16(acc[j * 2], al, bh[0], bh[1]);
                mma_bf16(acc[j * 2 + 1], al, bh[2], bh[3]);
                ldsm_x4t(smem_u32(&sBl[rowm * 136 + coln]), bl);
                mma_bf16(acc[j * 2], ah, bl[0], bl[1]);
                mma_bf16(acc[j * 2 + 1], ah, bl[2], bl[3]);
            }
        }
    }
    int o = (ogrp << 4) + (lane >> 2);
#pragma unroll
    for (int f = 0; f < 8; f++) {
        int n = n0 + (ngrp << 6) + ((f >> 1) << 4) + ((f & 1) << 3) + ((lane & 3) << 1);
        size_t off = ((size_t)(b << 6) + o) * Nn + n;
        float2 xv = *(const float2*)&x[off];
        *(float2*)&out[off] = make_float2(acc[f].x + xv.x, acc[f].y + xv.y);
        size_t off2 = off + (size_t)8 * Nn;
        float2 xv2 = *(const float2*)&x[off2];
        *(float2*)&out[off2] = make_float2(acc[f].z + xv2.x, acc[f].w + xv2.y);
    }
}

// ---------------- launch ----------------------------------------------------
extern "C" void kernel_launch(void* const* d_in, const int* in_sizes, int n_in,
                              void* d_out, int out_size) {
    const float* x      = (const float*)d_in[0];
    const float* wphi   = (const float*)d_in[1];
    const float* wtheta = (const float*)d_in[2];
    const float* wg     = (const float*)d_in[3];
    const float* wmask  = (const float*)d_in[4];
    const float* wmv    = (const float*)d_in[5];
    const float* wmk    = (const float*)d_in[6];
    float* out = (float*)d_out;

    cudaFuncSetAttribute(k2_P_mma, cudaFuncAttributeMaxDynamicSharedMemorySize, 55296);
    cudaFuncSetAttribute(k3_att_mma, cudaFuncAttributeMaxDynamicSharedMemorySize, 69632);
    cudaFuncSetAttribute(k4_out_mma, cudaFuncAttributeMaxDynamicSharedMemorySize, 53248);

    k0_prep<<<128, 256>>>(wmv, wg);
    k0w_split<<<1024, 256>>>(wmk);
    k1_channel<<<dim3(32, 16), 256>>>(x, wphi, wtheta);
    k2_P_mma<<<dim3(32, 8), 256, 55296>>>();
    k3_att_mma<<<dim3(8, 8, 32), 256, 69632>>>();
    k5_gmz<<<dim3(32, 16), 256>>>(wmask);
    k4_out_mma<<<dim3(32, 8), 256, 53248>>>(x, out);
}

// round 7
// speedup vs baseline: 1.7057x; 1.1507x over previous
#include <cuda_runtime.h>
#include <cuda_bf16.h>
#include <cstdint>

#define Bq 32
#define Cc 64
#define Nn 1024

typedef unsigned long long ull;

// ---------------- scratch (device globals) ----------------------------------
__device__ __nv_bfloat16 g_phiH[Bq * Cc * Nn];  // [b][c][m]
__device__ __nv_bfloat16 g_phiL[Bq * Cc * Nn];
__device__ __nv_bfloat16 g_wmkH[Nn * Nn];       // [k][m]
__device__ __nv_bfloat16 g_wmkL[Nn * Nn];
__device__ __nv_bfloat16 g_thH[Bq * Cc * Nn];   // [b][c][n] theta hi/lo
__device__ __nv_bfloat16 g_thL[Bq * Cc * Nn];
__device__ __nv_bfloat16 g_PH[Bq * Cc * Nn];    // [b][c][k] P hi/lo
__device__ __nv_bfloat16 g_PL[Bq * Cc * Nn];
__device__ float g_gm[Bq * Cc * Nn];            // [b][c][n]
__device__ __nv_bfloat16 g_EH[(size_t)Bq * Nn * Nn];  // [b][k][n] exp hi (64MB)
__device__ __nv_bfloat16 g_EL[(size_t)Bq * Nn * Nn];  // [b][k][n] exp lo (64MB)
__device__ float g_Z[Bq * Nn];
__device__ float g_wgv[Cc * Cc];
__device__ __nv_bfloat16 g_gzH[Bq * Cc * Nn];   // [b][o][m] (w_mask@gm)/Z hi/lo
__device__ __nv_bfloat16 g_gzL[Bq * Cc * Nn];

// ---------------- f32x2 helpers ---------------------------------------------
__device__ __forceinline__ ull pk2(float lo, float hi) {
    ull r;
    asm("mov.b64 %0, {%1, %2};" : "=l"(r) : "f"(lo), "f"(hi));
    return r;
}
__device__ __forceinline__ void fma2(ull& d, ull a, ull b) {
    asm("fma.rn.f32x2 %0, %1, %2, %0;" : "+l"(d) : "l"(a), "l"(b));
}
__device__ __forceinline__ float2 upk2(ull v) {
    float2 r;
    asm("mov.b64 {%0, %1}, %2;" : "=f"(r.x), "=f"(r.y) : "l"(v));
    return r;
}

// ---------------- mma.sync helpers ------------------------------------------
__device__ __forceinline__ uint32_t smem_u32(const void* p) {
    uint32_t a;
    asm("{ .reg .u64 t; cvta.to.shared.u64 t, %1; cvt.u32.u64 %0, t; }"
        : "=r"(a) : "l"(p));
    return a;
}
__device__ __forceinline__ void ldsm_x4(uint32_t addr, uint32_t r[4]) {
    asm volatile("ldmatrix.sync.aligned.m8n8.x4.shared.b16 {%0,%1,%2,%3}, [%4];"
                 : "=r"(r[0]), "=r"(r[1]), "=r"(r[2]), "=r"(r[3]) : "r"(addr));
}
__device__ __forceinline__ void ldsm_x4t(uint32_t addr, uint32_t r[4]) {
    asm volatile("ldmatrix.sync.aligned.m8n8.x4.trans.shared.b16 {%0,%1,%2,%3}, [%4];"
                 : "=r"(r[0]), "=r"(r[1]), "=r"(r[2]), "=r"(r[3]) : "r"(addr));
}
__device__ __forceinline__ void mma_bf16(float4& d, const uint32_t a[4],
                                         uint32_t b0, uint32_t b1) {
    asm volatile(
        "mma.sync.aligned.m16n8k16.row.col.f32.bf16.bf16.f32 "
        "{%0,%1,%2,%3}, {%4,%5,%6,%7}, {%8,%9}, {%0,%1,%2,%3};"
        : "+f"(d.x), "+f"(d.y), "+f"(d.z), "+f"(d.w)
        : "r"(a[0]), "r"(a[1]), "r"(a[2]), "r"(a[3]), "r"(b0), "r"(b1));
}
__device__ __forceinline__ uint32_t bfpack(float a, float b) {
    __nv_bfloat162 h;
    h.x = __float2bfloat16(a); h.y = __float2bfloat16(b);
    return *(uint32_t*)&h;
}
__device__ __forceinline__ void split4(float4 v, uint2& hi, uint2& lo) {
    uint32_t hA = bfpack(v.x, v.y), hB = bfpack(v.z, v.w);
    __nv_bfloat162* hp = (__nv_bfloat162*)&hA;
    __nv_bfloat162* hq = (__nv_bfloat162*)&hB;
    uint32_t lA = bfpack(v.x - __bfloat162float(hp->x), v.y - __bfloat162float(hp->y));
    uint32_t lB = bfpack(v.z - __bfloat162float(hq->x), v.w - __bfloat162float(hq->y));
    hi = make_uint2(hA, hB); lo = make_uint2(lA, lB);
}

// ---------------- K0: zero Z, wgv = w_mv @ w_g ------------------------------
__global__ void k0_prep(const float* __restrict__ wmv, const float* __restrict__ wg) {
    int t = blockIdx.x * blockDim.x + threadIdx.x;
    if (t < Bq * Nn) g_Z[t] = 0.0f;
    if (t < Cc * Cc) {
        int d = t >> 6, ci = t & 63;
        float s = 0.0f;
#pragma unroll
        for (int c = 0; c < 64; c++) s += wmv[d * 64 + c] * wg[c * 64 + ci];
        g_wgv[t] = s;
    }
}

// ---------------- K0w: split wmk into bf16 hi/lo ----------------------------
__global__ __launch_bounds__(256) void k0w_split(const float* __restrict__ wmk) {
    int i = blockIdx.x * 256 + threadIdx.x;
    float4 v = ((const float4*)wmk)[i];
    uint2 hi, lo;
    split4(v, hi, lo);
    ((uint2*)g_wmkH)[i] = hi;
    ((uint2*)g_wmkL)[i] = lo;
}

// ---------------- K1: channel GEMMs: phi, theta (both bf16 split), gm -------
__global__ __launch_bounds__(256) void k1_channel(
    const float* __restrict__ x, const float* __restrict__ wphi,
    const float* __restrict__ wtheta) {
    __shared__ __align__(16) float sX[64][68];
    __shared__ __align__(16) float sW[64][68];
    int b = blockIdx.x, n0 = blockIdx.y << 6;
    int t = threadIdx.x, ty = t >> 4, tx = t & 15;

#pragma unroll
    for (int i = 0; i < 16; i++) {
        int idx = t + (i << 8);
        int ci = idx >> 6, nn = idx & 63;
        sX[ci][nn] = x[((b << 6) + ci) * Nn + n0 + nn];
    }

    const float* Ws[3] = {wphi, wtheta, g_wgv};

    for (int p = 0; p < 3; p++) {
        __syncthreads();
#pragma unroll
        for (int i = 0; i < 16; i++) {
            int idx = t + (i << 8);
            int c = idx >> 6, ci = idx & 63;
            sW[ci][c] = Ws[p][idx];
        }
        __syncthreads();

        ull acc[4][2] = {};
#pragma unroll 8
        for (int ci = 0; ci < 64; ci++) {
            float4 av = *(const float4*)&sW[ci][ty << 2];
            ulonglong2 bv = *(const ulonglong2*)&sX[ci][tx << 2];
            ull a0 = pk2(av.x, av.x), a1 = pk2(av.y, av.y);
            ull a2 = pk2(av.z, av.z), a3 = pk2(av.w, av.w);
            fma2(acc[0][0], a0, bv.x); fma2(acc[0][1], a0, bv.y);
            fma2(acc[1][0], a1, bv.x); fma2(acc[1][1], a1, bv.y);
            fma2(acc[2][0], a2, bv.x); fma2(acc[2][1], a2, bv.y);
            fma2(acc[3][0], a3, bv.x); fma2(acc[3][1], a3, bv.y);
        }
        float v[4][4];
#pragma unroll
        for (int i = 0; i < 4; i++) {
            float2 v0 = upk2(acc[i][0]), v1 = upk2(acc[i][1]);
            v[i][0] = v0.x; v[i][1] = v0.y; v[i][2] = v1.x; v[i][3] = v1.y;
        }
        if (p == 2) {
            float* O = g_gm + (b << 6) * Nn + n0;
#pragma unroll
            for (int i = 0; i < 4; i++)
                *(float4*)&O[((ty << 2) + i) * Nn + (tx << 2)] =
                    make_float4(v[i][0], v[i][1], v[i][2], v[i][3]);
        } else {
            __nv_bfloat16* H = (p == 0 ? g_phiH : g_thH);
            __nv_bfloat16* L = (p == 0 ? g_phiL : g_thL);
#pragma unroll
            for (int i = 0; i < 4; i++) {
                int base = ((b << 6) + (ty << 2) + i) * Nn + n0 + (tx << 2);
                float4 pv = make_float4(v[i][0], v[i][1], v[i][2], v[i][3]);
                uint2 hi, lo;
                split4(pv, hi, lo);
                *(uint2*)&H[base] = hi;
                *(uint2*)&L[base] = lo;
            }
        }
    }
}

// ---------------- K2: P = phi @ wmk^T  (mma.sync bf16x3) --------------------
// grid (32 b, 8 ktile), block 256 = 8 warps. Warp tile 16c x 64k. K-chunk 128.
__global__ __launch_bounds__(256, 2) void k2_P_mma(void) {
    extern __shared__ __align__(16) char sm2[];
    __nv_bfloat16* sAh = (__nv_bfloat16*)sm2;               // [64][136]
    __nv_bfloat16* sAl = (__nv_bfloat16*)(sm2 + 17408);
    __nv_bfloat16* sBh = (__nv_bfloat16*)(sm2 + 34816);     // [128][136]
    __nv_bfloat16* sBl = (__nv_bfloat16*)(sm2 + 69632);
    int b = blockIdx.x, k0 = blockIdx.y << 7;
    int t = threadIdx.x, w = t >> 5, lane = t & 31;
    int cgrp = w & 3, kgrp = w >> 2;

    const __nv_bfloat16* Ah = g_phiH + (size_t)(b << 6) * Nn;
    const __nv_bfloat16* Al = g_phiL + (size_t)(b << 6) * Nn;

    float4 acc[8] = {};
    int lr = lane & 15, lh = lane >> 4;
    int bq = lane >> 3, br = lane & 7;

    for (int mc = 0; mc < Nn; mc += 128) {
        __syncthreads();
#pragma unroll
        for (int i = 0; i < 4; i++) {
            int lin = t + (i << 8);
            int r = lin >> 4, q = lin & 15;
            *(uint4*)&sAh[r * 136 + (q << 3)] =
                *(const uint4*)&Ah[(size_t)r * Nn + mc + (q << 3)];
            *(uint4*)&sAl[r * 136 + (q << 3)] =
                *(const uint4*)&Al[(size_t)r * Nn + mc + (q << 3)];
        }
#pragma unroll
        for (int i = 0; i < 8; i++) {
            int lin = t + (i << 8);
            int r = lin >> 4, q = lin & 15;
            *(uint4*)&sBh[r * 136 + (q << 3)] =
                *(const uint4*)&g_wmkH[(size_t)(k0 + r) * Nn + mc + (q << 3)];
            *(uint4*)&sBl[r * 136 + (q << 3)] =
                *(const uint4*)&g_wmkL[(size_t)(k0 + r) * Nn + mc + (q << 3)];
        }
        __syncthreads();
#pragma unroll
        for (int kk = 0; kk < 8; kk++) {
            uint32_t ah[4], al[4];
            ldsm_x4(smem_u32(&sAh[(cgrp * 16 + lr) * 136 + kk * 16 + lh * 8]), ah);
            ldsm_x4(smem_u32(&sAl[(cgrp * 16 + lr) * 136 + kk * 16 + lh * 8]), al);
#pragma unroll
            for (int j = 0; j < 4; j++) {
                int rowb = (kgrp << 6) + (j << 4) + ((bq >> 1) << 3) + br;
                int colb = (kk << 4) + ((bq & 1) << 3);
                uint32_t bh[4], bl[4];
                ldsm_x4(smem_u32(&sBh[rowb * 136 + colb]), bh);
                mma_bf16(acc[j * 2], ah, bh[0], bh[1]);
                mma_bf16(acc[j * 2 + 1], ah, bh[2], bh[3]);
                mma_bf16(acc[j * 2], al, bh[0], bh[1]);
                mma_bf16(acc[j * 2 + 1], al, bh[2], bh[3]);
                ldsm_x4(smem_u32(&sBl[rowb * 136 + colb]), bl);
                mma_bf16(acc[j * 2], ah, bl[0], bl[1]);
                mma_bf16(acc[j * 2 + 1], ah, bl[2], bl[3]);
            }
        }
    }
    // epilogue: store P as bf16 hi/lo (pre-split for k3)
    int m = (cgrp << 4) + (lane >> 2);
    size_t prow = ((size_t)(b << 6) + m) * Nn + k0;
#pragma unroll
    for (int f = 0; f < 8; f++) {
        int n = (kgrp << 6) + ((f >> 1) << 4) + ((f & 1) << 3) + ((lane & 3) << 1);
        {
            float vx = acc[f].x, vy = acc[f].y;
            uint32_t h = bfpack(vx, vy);
            __nv_bfloat162* hp = (__nv_bfloat162*)&h;
            uint32_t l = bfpack(vx - __bfloat162float(hp->x),
                                vy - __bfloat162float(hp->y));
            *(uint32_t*)&g_PH[prow + n] = h;
            *(uint32_t*)&g_PL[prow + n] = l;
        }
        {
            float vx = acc[f].z, vy = acc[f].w;
            uint32_t h = bfpack(vx, vy);
            __nv_bfloat162* hp = (__nv_bfloat162*)&h;
            uint32_t l = bfpack(vx - __bfloat162float(hp->x),
                                vy - __bfloat162float(hp->y));
            *(uint32_t*)&g_PH[prow + 8 * Nn + n] = h;
            *(uint32_t*)&g_PL[prow + 8 * Nn + n] = l;
        }
    }
}

// ---------------- K3: Et = exp(P^T theta), bf16 hi/lo out, Z sums -----------
// grid (8 ktile, 8 ntile, 32 b), block 256. CTA tile 128k x 128n, c = 64.
__global__ __launch_bounds__(256, 2) void k3_att_mma(void) {
    extern __shared__ __align__(16) char sm3[];
    __nv_bfloat16* sPh = (__nv_bfloat16*)sm3;              // [64][136]
    __nv_bfloat16* sPl = (__nv_bfloat16*)(sm3 + 17408);
    __nv_bfloat16* sTh = (__nv_bfloat16*)(sm3 + 34816);
    __nv_bfloat16* sTl = (__nv_bfloat16*)(sm3 + 52224);
    int b = blockIdx.z, k0 = blockIdx.x << 7, n0 = blockIdx.y << 7;
    int t = threadIdx.x, w = t >> 5, lane = t & 31;
    int kw = w & 3, nw = w >> 2;

    // raw-copy staging (pre-split by producers)
#pragma unroll
    for (int i = 0; i < 4; i++) {
        int lin = t + (i << 8);
        int r = lin >> 4, q = lin & 15;
        size_t pofs = ((size_t)(b << 6) + r) * Nn + k0 + (q << 3);
        size_t tofs = ((size_t)(b << 6) + r) * Nn + n0 + (q << 3);
        *(uint4*)&sPh[r * 136 + (q << 3)] = *(const uint4*)&g_PH[pofs];
        *(uint4*)&sPl[r * 136 + (q << 3)] = *(const uint4*)&g_PL[pofs];
        *(uint4*)&sTh[r * 136 + (q << 3)] = *(const uint4*)&g_thH[tofs];
        *(uint4*)&sTl[r * 136 + (q << 3)] = *(const uint4*)&g_thL[tofs];
    }
    __syncthreads();

    float4 acc[2][8] = {};
    int bq = lane >> 3, br = lane & 7;
#pragma unroll
    for (int kk = 0; kk < 4; kk++) {
        int c0 = kk << 4;
        uint32_t ah[2][4], al[2][4];
#pragma unroll
        for (int mt = 0; mt < 2; mt++) {
            int m0 = (kw << 5) + (mt << 4);
            int rowc = c0 + ((bq >> 1) << 3) + br;
            int colm = m0 + ((bq & 1) << 3);
            ldsm_x4t(smem_u32(&sPh[rowc * 136 + colm]), ah[mt]);
            ldsm_x4t(smem_u32(&sPl[rowc * 136 + colm]), al[mt]);
        }
#pragma unroll
        for (int j = 0; j < 4; j++) {
            int rowc = c0 + ((bq & 1) << 3) + br;
            int coln = (nw << 6) + (j << 4) + ((bq >> 1) << 3);
            uint32_t bh[4], bl[4];
            ldsm_x4t(smem_u32(&sTh[rowc * 136 + coln]), bh);
            ldsm_x4t(smem_u32(&sTl[rowc * 136 + coln]), bl);
#pragma unroll
            for (int mt = 0; mt < 2; mt++) {
                mma_bf16(acc[mt][j * 2], ah[mt], bh[0], bh[1]);
                mma_bf16(acc[mt][j * 2 + 1], ah[mt], bh[2], bh[3]);
                mma_bf16(acc[mt][j * 2], al[mt], bh[0], bh[1]);
                mma_bf16(acc[mt][j * 2 + 1], al[mt], bh[2], bh[3]);
                mma_bf16(acc[mt][j * 2], ah[mt], bl[0], bl[1]);
                mma_bf16(acc[mt][j * 2 + 1], ah[mt], bl[2], bl[3]);
            }
        }
    }

    __syncthreads();
    __nv_bfloat16* sEH = (__nv_bfloat16*)sm3;
    __nv_bfloat16* sEL = (__nv_bfloat16*)(sm3 + 34816);
#pragma unroll
    for (int mt = 0; mt < 2; mt++) {
        int krow = (kw << 5) + (mt << 4) + (lane >> 2);
        float sA = 0.f, sB = 0.f;
#pragma unroll
        for (int j = 0; j < 8; j++) {
            int nc = (nw << 6) + (j << 3) + ((lane & 3) << 1);
            float ex = __expf(acc[mt][j].x), ey = __expf(acc[mt][j].y);
            float ez = __expf(acc[mt][j].z), ew = __expf(acc[mt][j].w);
            sA += ex + ey; sB += ez + ew;
            uint32_t h0 = bfpack(ex, ey);
            __nv_bfloat162* hp = (__nv_bfloat162*)&h0;
            uint32_t l0 = bfpack(ex - __bfloat162float(hp->x),
                                 ey - __bfloat162float(hp->y));
            *(uint32_t*)&sEH[krow * 136 + nc] = h0;
            *(uint32_t*)&sEL[krow * 136 + nc] = l0;
            uint32_t h1 = bfpack(ez, ew);
            __nv_bfloat162* hq = (__nv_bfloat162*)&h1;
            uint32_t l1 = bfpack(ez - __bfloat162float(hq->x),
                                 ew - __bfloat162float(hq->y));
            *(uint32_t*)&sEH[(krow + 8) * 136 + nc] = h1;
            *(uint32_t*)&sEL[(krow + 8) * 136 + nc] = l1;
        }
        sA += __shfl_xor_sync(0xffffffffu, sA, 1);
        sA += __shfl_xor_sync(0xffffffffu, sA, 2);
        sB += __shfl_xor_sync(0xffffffffu, sB, 1);
        sB += __shfl_xor_sync(0xffffffffu, sB, 2);
        if ((lane & 3) == 0) {
            atomicAdd(&g_Z[b * Nn + k0 + krow], sA);
            atomicAdd(&g_Z[b * Nn + k0 + krow + 8], sB);
        }
    }
    __syncthreads();
#pragma unroll
    for (int i = 0; i < 8; i++) {
        int lin = t + (i << 8);
        int r = lin >> 4, q = lin & 15;
        size_t off = ((size_t)(b * Nn + k0 + r)) * Nn + n0 + (q << 3);
        *(uint4*)&g_EH[off] = *(uint4*)&sEH[r * 136 + (q << 3)];
        *(uint4*)&g_EL[off] = *(uint4*)&sEL[r * 136 + (q << 3)];
    }
}

// ---------------- K5: gz = (wmask@gm)/Z, bf16 hi/lo out ---------------------
__global__ __launch_bounds__(256) void k5_gmz(const float* __restrict__ wmask) {
    __shared__ __align__(16) float smG[64][68];
    __shared__ __align__(16) float smW[64][68];
    __shared__ float sz[64];
    int b = blockIdx.x, m0 = blockIdx.y << 6;
    int t = threadIdx.x;
    const float* gm = g_gm + (b << 6) * Nn;
#pragma unroll
    for (int i = 0; i < 4; i++) {
        int idx = t + (i << 8);
        int r = idx >> 4, c4 = idx & 15;
        *(float4*)&smG[r][c4 << 2] = *(const float4*)&gm[r * Nn + m0 + (c4 << 2)];
        *(float4*)&smW[r][c4 << 2] = *(const float4*)&wmask[r * 64 + (c4 << 2)];
    }
    if (t < 64) sz[t] = 1.0f / g_Z[b * Nn + m0 + t];
    __syncthreads();
    int m = t & 63, og = t >> 6;
    float inv = sz[m];
#pragma unroll
    for (int q = 0; q < 16; q++) {
        int o = (og << 4) + q;
        float s = 0.0f;
#pragma unroll
        for (int c = 0; c < 64; c++) s += smW[o][c] * smG[c][m];
        float v = s * inv;
        size_t idx = ((size_t)(b << 6) + o) * Nn + m0 + m;
        __nv_bfloat16 h = __float2bfloat16(v);
        g_gzH[idx] = h;
        g_gzL[idx] = __float2bfloat16(v - __bfloat162float(h));
    }
}

// ---------------- K4: out[o][n] = sum_m gz[o][m] E[m][n] + x ----------------
// grid (32 b, 8 ntile), block 256. Warp tile 16o x 64n, K=1024(m), chunk 64.
__global__ __launch_bounds__(256, 2) void k4_out_mma(
    const float* __restrict__ x, float* __restrict__ out) {
    extern __shared__ __align__(16) char sm4[];
    __nv_bfloat16* sAh = (__nv_bfloat16*)sm4;               // [64 o][72 m]
    __nv_bfloat16* sAl = (__nv_bfloat16*)(sm4 + 9216);
    __nv_bfloat16* sBh = (__nv_bfloat16*)(sm4 + 18432);     // [64 m][136 n]
    __nv_bfloat16* sBl = (__nv_bfloat16*)(sm4 + 35840);
    int b = blockIdx.x, n0 = blockIdx.y << 7;
    int t = threadIdx.x, w = t >> 5, lane = t & 31;
    int ogrp = w & 3, ngrp = w >> 2;

    float4 acc[8] = {};
    int lr = lane & 15, lh = lane >> 4;
    int bq = lane >> 3, br = lane & 7;

    for (int mc = 0; mc < Nn; mc += 64) {
        __syncthreads();
        // raw copies: gzH/gzL [o][m], EH/EL [m][n]
#pragma unroll
        for (int i = 0; i < 2; i++) {
            int lin = t + (i << 8);
            int r = lin >> 3, q = lin & 7;
            size_t gofs = ((size_t)(b << 6) + r) * Nn + mc + (q << 3);
            *(uint4*)&sAh[r * 72 + (q << 3)] = *(const uint4*)&g_gzH[gofs];
            *(uint4*)&sAl[r * 72 + (q << 3)] = *(const uint4*)&g_gzL[gofs];
        }
#pragma unroll
        for (int i = 0; i < 4; i++) {
            int lin = t + (i << 8);
            int r = lin >> 4, q = lin & 15;
            size_t off = ((size_t)(b * Nn) + mc + r) * Nn + n0 + (q << 3);
            *(uint4*)&sBh[r * 136 + (q << 3)] = *(const uint4*)&g_EH[off];
            *(uint4*)&sBl[r * 136 + (q << 3)] = *(const uint4*)&g_EL[off];
        }
        __syncthreads();
#pragma unroll
        for (int kk = 0; kk < 4; kk++) {
            uint32_t ah[4], al[4];
            ldsm_x4(smem_u32(&sAh[(ogrp * 16 + lr) * 72 + kk * 16 + lh * 8]), ah);
            ldsm_x4(smem_u32(&sAl[(ogrp * 16 + lr) * 72 + kk * 16 + lh * 8]), al);
#pragma unroll
            for (int j = 0; j < 4; j++) {
                int rowm = (kk << 4) + ((bq & 1) << 3) + br;
                int coln = (ngrp << 6) + (j << 4) + ((bq >> 1) << 3);
                uint32_t bh[4], bl[4];
                ldsm_x4t(smem_u32(&sBh[rowm * 136 + coln]), bh);
                mma_bf16(acc[j * 2], ah, bh[0], bh[1]);
                mma_bf16(acc[j * 2 + 1], ah, bh[2], bh[3]);
                mma_bf16(acc[j * 2], al, bh[0], bh[1]);
                mma_bf16(acc[j * 2 + 1], al, bh[2], bh[3]);
                ldsm_x4t(smem_u32(&sBl[rowm * 136 + coln]), bl);
                mma_bf16(acc[j * 2], ah, bl[0], bl[1]);
                mma_bf16(acc[j * 2 + 1], ah, bl[2], bl[3]);
            }
        }
    }
    int o = (ogrp << 4) + (lane >> 2);
#pragma unroll
    for (int f = 0; f < 8; f++) {
        int n = n0 + (ngrp << 6) + ((f >> 1) << 4) + ((f & 1) << 3) + ((lane & 3) << 1);
        size_t off = ((size_t)(b << 6) + o) * Nn + n;
        float2 xv = *(const float2*)&x[off];
        *(float2*)&out[off] = make_float2(acc[f].x + xv.x, acc[f].y + xv.y);
        size_t off2 = off + (size_t)8 * Nn;
        float2 xv2 = *(const float2*)&x[off2];
        *(float2*)&out[off2] = make_float2(acc[f].z + xv2.x, acc[f].w + xv2.y);
    }
}

// ---------------- launch ----------------------------------------------------
extern "C" void kernel_launch(void* const* d_in, const int* in_sizes, int n_in,
                              void* d_out, int out_size) {
    const float* x      = (const float*)d_in[0];
    const float* wphi   = (const float*)d_in[1];
    const float* wtheta = (const float*)d_in[2];
    const float* wg     = (const float*)d_in[3];
    const float* wmask  = (const float*)d_in[4];
    const float* wmv    = (const float*)d_in[5];
    const float* wmk    = (const float*)d_in[6];
    float* out = (float*)d_out;

    cudaFuncSetAttribute(k2_P_mma, cudaFuncAttributeMaxDynamicSharedMemorySize, 104448);
    cudaFuncSetAttribute(k3_att_mma, cudaFuncAttributeMaxDynamicSharedMemorySize, 69632);
    cudaFuncSetAttribute(k4_out_mma, cudaFuncAttributeMaxDynamicSharedMemorySize, 53248);

    k0_prep<<<128, 256>>>(wmv, wg);
    k0w_split<<<1024, 256>>>(wmk);
    k1_channel<<<dim3(32, 16), 256>>>(x, wphi, wtheta);
    k2_P_mma<<<dim3(32, 8), 256, 104448>>>();
    k3_att_mma<<<dim3(8, 8, 32), 256, 69632>>>();
    k5_gmz<<<dim3(32, 16), 256>>>(wmask);
    k4_out_mma<<<dim3(32, 8), 256, 53248>>>(x, out);
}

// round 8
// speedup vs baseline: 1.8449x; 1.0816x over previous
#include <cuda_runtime.h>
#include <cuda_bf16.h>
#include <cstdint>

#define Bq 32
#define Cc 64
#define Nn 1024

typedef unsigned long long ull;

// ---------------- scratch (device globals) ----------------------------------
__device__ __nv_bfloat16 g_phiH[Bq * Cc * Nn];  // [b][c][m]
__device__ __nv_bfloat16 g_phiL[Bq * Cc * Nn];
__device__ __nv_bfloat16 g_wmkH[Nn * Nn];       // [k][m]
__device__ __nv_bfloat16 g_wmkL[Nn * Nn];
__device__ __nv_bfloat16 g_thH[Bq * Cc * Nn];   // [b][c][n] theta hi/lo
__device__ __nv_bfloat16 g_thL[Bq * Cc * Nn];
__device__ __nv_bfloat16 g_PH[Bq * Cc * Nn];    // [b][c][k] P hi/lo
__device__ __nv_bfloat16 g_PL[Bq * Cc * Nn];
__device__ float g_gm[Bq * Cc * Nn];            // [b][c][n]
__device__ __nv_bfloat16 g_EH[(size_t)Bq * Nn * Nn];  // [b][k][n] exp hi (64MB)
__device__ __nv_bfloat16 g_EL[(size_t)Bq * Nn * Nn];  // [b][k][n] exp lo (64MB)
__device__ float g_Z[Bq * Nn];
__device__ float g_wgv[Cc * Cc];
__device__ __nv_bfloat16 g_gzH[Bq * Cc * Nn];   // [b][o][m] (w_mask@gm)/Z hi/lo
__device__ __nv_bfloat16 g_gzL[Bq * Cc * Nn];

// ---------------- f32x2 helpers ---------------------------------------------
__device__ __forceinline__ ull pk2(float lo, float hi) {
    ull r;
    asm("mov.b64 %0, {%1, %2};" : "=l"(r) : "f"(lo), "f"(hi));
    return r;
}
__device__ __forceinline__ void fma2(ull& d, ull a, ull b) {
    asm("fma.rn.f32x2 %0, %1, %2, %0;" : "+l"(d) : "l"(a), "l"(b));
}
__device__ __forceinline__ float2 upk2(ull v) {
    float2 r;
    asm("mov.b64 {%0, %1}, %2;" : "=f"(r.x), "=f"(r.y) : "l"(v));
    return r;
}

// ---------------- mma.sync / cp.async helpers -------------------------------
__device__ __forceinline__ uint32_t smem_u32(const void* p) {
    uint32_t a;
    asm("{ .reg .u64 t; cvta.to.shared.u64 t, %1; cvt.u32.u64 %0, t; }"
        : "=r"(a) : "l"(p));
    return a;
}
__device__ __forceinline__ void ldsm_x4(uint32_t addr, uint32_t r[4]) {
    asm volatile("ldmatrix.sync.aligned.m8n8.x4.shared.b16 {%0,%1,%2,%3}, [%4];"
                 : "=r"(r[0]), "=r"(r[1]), "=r"(r[2]), "=r"(r[3]) : "r"(addr));
}
__device__ __forceinline__ void ldsm_x4t(uint32_t addr, uint32_t r[4]) {
    asm volatile("ldmatrix.sync.aligned.m8n8.x4.trans.shared.b16 {%0,%1,%2,%3}, [%4];"
                 : "=r"(r[0]), "=r"(r[1]), "=r"(r[2]), "=r"(r[3]) : "r"(addr));
}
__device__ __forceinline__ void mma_bf16(float4& d, const uint32_t a[4],
                                         uint32_t b0, uint32_t b1) {
    asm volatile(
        "mma.sync.aligned.m16n8k16.row.col.f32.bf16.bf16.f32 "
        "{%0,%1,%2,%3}, {%4,%5,%6,%7}, {%8,%9}, {%0,%1,%2,%3};"
        : "+f"(d.x), "+f"(d.y), "+f"(d.z), "+f"(d.w)
        : "r"(a[0]), "r"(a[1]), "r"(a[2]), "r"(a[3]), "r"(b0), "r"(b1));
}
__device__ __forceinline__ void cpa16(uint32_t s, const void* g) {
    asm volatile("cp.async.cg.shared.global [%0], [%1], 16;" :: "r"(s), "l"(g));
}
#define CPA_COMMIT() asm volatile("cp.async.commit_group;" ::: "memory")
#define CPA_WAIT(n) asm volatile("cp.async.wait_group %0;" :: "n"(n) : "memory")

__device__ __forceinline__ uint32_t bfpack(float a, float b) {
    __nv_bfloat162 h;
    h.x = __float2bfloat16(a); h.y = __float2bfloat16(b);
    return *(uint32_t*)&h;
}
__device__ __forceinline__ void split4(float4 v, uint2& hi, uint2& lo) {
    uint32_t hA = bfpack(v.x, v.y), hB = bfpack(v.z, v.w);
    __nv_bfloat162* hp = (__nv_bfloat162*)&hA;
    __nv_bfloat162* hq = (__nv_bfloat162*)&hB;
    uint32_t lA = bfpack(v.x - __bfloat162float(hp->x), v.y - __bfloat162float(hp->y));
    uint32_t lB = bfpack(v.z - __bfloat162float(hq->x), v.w - __bfloat162float(hq->y));
    hi = make_uint2(hA, hB); lo = make_uint2(lA, lB);
}

// ---------------- K0: zero Z, wgv = w_mv @ w_g ------------------------------
__global__ void k0_prep(const float* __restrict__ wmv, const float* __restrict__ wg) {
    int t = blockIdx.x * blockDim.x + threadIdx.x;
    if (t < Bq * Nn) g_Z[t] = 0.0f;
    if (t < Cc * Cc) {
        int d = t >> 6, ci = t & 63;
        float s = 0.0f;
#pragma unroll
        for (int c = 0; c < 64; c++) s += wmv[d * 64 + c] * wg[c * 64 + ci];
        g_wgv[t] = s;
    }
}

// ---------------- K0w: split wmk into bf16 hi/lo ----------------------------
__global__ __launch_bounds__(256) void k0w_split(const float* __restrict__ wmk) {
    int i = blockIdx.x * 256 + threadIdx.x;
    float4 v = ((const float4*)wmk)[i];
    uint2 hi, lo;
    split4(v, hi, lo);
    ((uint2*)g_wmkH)[i] = hi;
    ((uint2*)g_wmkL)[i] = lo;
}

// ---------------- K1: channel GEMMs: phi, theta (both bf16 split), gm -------
__global__ __launch_bounds__(256) void k1_channel(
    const float* __restrict__ x, const float* __restrict__ wphi,
    const float* __restrict__ wtheta) {
    __shared__ __align__(16) float sX[64][68];
    __shared__ __align__(16) float sW[64][68];
    int b = blockIdx.x, n0 = blockIdx.y << 6;
    int t = threadIdx.x, ty = t >> 4, tx = t & 15;

#pragma unroll
    for (int i = 0; i < 16; i++) {
        int idx = t + (i << 8);
        int ci = idx >> 6, nn = idx & 63;
        sX[ci][nn] = x[((b << 6) + ci) * Nn + n0 + nn];
    }

    const float* Ws[3] = {wphi, wtheta, g_wgv};

    for (int p = 0; p < 3; p++) {
        __syncthreads();
#pragma unroll
        for (int i = 0; i < 16; i++) {
            int idx = t + (i << 8);
            int c = idx >> 6, ci = idx & 63;
            sW[ci][c] = Ws[p][idx];
        }
        __syncthreads();

        ull acc[4][2] = {};
#pragma unroll 8
        for (int ci = 0; ci < 64; ci++) {
            float4 av = *(const float4*)&sW[ci][ty << 2];
            ulonglong2 bv = *(const ulonglong2*)&sX[ci][tx << 2];
            ull a0 = pk2(av.x, av.x), a1 = pk2(av.y, av.y);
            ull a2 = pk2(av.z, av.z), a3 = pk2(av.w, av.w);
            fma2(acc[0][0], a0, bv.x); fma2(acc[0][1], a0, bv.y);
            fma2(acc[1][0], a1, bv.x); fma2(acc[1][1], a1, bv.y);
            fma2(acc[2][0], a2, bv.x); fma2(acc[2][1], a2, bv.y);
            fma2(acc[3][0], a3, bv.x); fma2(acc[3][1], a3, bv.y);
        }
        float v[4][4];
#pragma unroll
        for (int i = 0; i < 4; i++) {
            float2 v0 = upk2(acc[i][0]), v1 = upk2(acc[i][1]);
            v[i][0] = v0.x; v[i][1] = v0.y; v[i][2] = v1.x; v[i][3] = v1.y;
        }
        if (p == 2) {
            float* O = g_gm + (b << 6) * Nn + n0;
#pragma unroll
            for (int i = 0; i < 4; i++)
                *(float4*)&O[((ty << 2) + i) * Nn + (tx << 2)] =
                    make_float4(v[i][0], v[i][1], v[i][2], v[i][3]);
        } else {
            __nv_bfloat16* H = (p == 0 ? g_phiH : g_thH);
            __nv_bfloat16* L = (p == 0 ? g_phiL : g_thL);
#pragma unroll
            for (int i = 0; i < 4; i++) {
                int base = ((b << 6) + (ty << 2) + i) * Nn + n0 + (tx << 2);
                float4 pv = make_float4(v[i][0], v[i][1], v[i][2], v[i][3]);
                uint2 hi, lo;
                split4(pv, hi, lo);
                *(uint2*)&H[base] = hi;
                *(uint2*)&L[base] = lo;
            }
        }
    }
}

// ---------------- K2: P = phi @ wmk^T  (mma.sync bf16x3, cp.async pipe) -----
// grid (32 b, 8 ktile), block 256 = 8 warps. Warp tile 16c x 64k. Chunk 64, 2 bufs.
// Buffer layout (bytes, per buf=55296): aH 0, aL 9216, bH 18432, bL 36864.
// A rows stride 144B (72 bf16), B rows stride 144B.
__global__ __launch_bounds__(256, 2) void k2_P_mma(void) {
    extern __shared__ __align__(16) char sm2[];
    uint32_t sb = smem_u32(sm2);
    int b = blockIdx.x, k0 = blockIdx.y << 7;
    int t = threadIdx.x, w = t >> 5, lane = t & 31;
    int cgrp = w & 3, kgrp = w >> 2;

    const __nv_bfloat16* Ah = g_phiH + (size_t)(b << 6) * Nn;
    const __nv_bfloat16* Al = g_phiL + (size_t)(b << 6) * Nn;

    float4 acc[8] = {};
    int lr = lane & 15, lh = lane >> 4;
    int bq = lane >> 3, br = lane & 7;

    // stage chunk mc into buffer buf
    auto stage = [&](int mc, int buf) {
        uint32_t base = sb + buf * 55296u;
        uint32_t aH = base, aL = base + 9216u, bH = base + 18432u, bL = base + 36864u;
#pragma unroll
        for (int i = 0; i < 2; i++) {
            int lin = t + (i << 8);
            int r = lin >> 3, q = lin & 7;
            cpa16(aH + r * 144 + (q << 4), &Ah[(size_t)r * Nn + mc + (q << 3)]);
            cpa16(aL + r * 144 + (q << 4), &Al[(size_t)r * Nn + mc + (q << 3)]);
        }
#pragma unroll
        for (int i = 0; i < 4; i++) {
            int lin = t + (i << 8);
            int r = lin >> 3, q = lin & 7;
            cpa16(bH + r * 144 + (q << 4), &g_wmkH[(size_t)(k0 + r) * Nn + mc + (q << 3)]);
            cpa16(bL + r * 144 + (q << 4), &g_wmkL[(size_t)(k0 + r) * Nn + mc + (q << 3)]);
        }
        CPA_COMMIT();
    };

    stage(0, 0);
    for (int ci = 0; ci < 16; ci++) {
        int buf = ci & 1;
        if (ci + 1 < 16) { stage((ci + 1) << 6, buf ^ 1); CPA_WAIT(1); }
        else { CPA_WAIT(0); }
        __syncthreads();
        uint32_t base = sb + buf * 55296u;
        uint32_t aH = base, aL = base + 9216u, bH = base + 18432u, bL = base + 36864u;
#pragma unroll
        for (int kk = 0; kk < 4; kk++) {
            uint32_t ah[4], al[4];
            uint32_t arow = (cgrp * 16 + lr) * 144 + kk * 32 + lh * 16;
            ldsm_x4(aH + arow, ah);
            ldsm_x4(aL + arow, al);
#pragma unroll
            for (int j = 0; j < 4; j++) {
                int rowb = (kgrp << 6) + (j << 4) + ((bq >> 1) << 3) + br;
                uint32_t boff = rowb * 144 + kk * 32 + ((bq & 1) << 4);
                uint32_t bh[4], bl[4];
                ldsm_x4(bH + boff, bh);
                mma_bf16(acc[j * 2], ah, bh[0], bh[1]);
                mma_bf16(acc[j * 2 + 1], ah, bh[2], bh[3]);
                mma_bf16(acc[j * 2], al, bh[0], bh[1]);
                mma_bf16(acc[j * 2 + 1], al, bh[2], bh[3]);
                ldsm_x4(bL + boff, bl);
                mma_bf16(acc[j * 2], ah, bl[0], bl[1]);
                mma_bf16(acc[j * 2 + 1], ah, bl[2], bl[3]);
            }
        }
        __syncthreads();
    }

    // epilogue: store P as bf16 hi/lo (pre-split for k3)
    int m = (cgrp << 4) + (lane >> 2);
    size_t prow = ((size_t)(b << 6) + m) * Nn + k0;
#pragma unroll
    for (int f = 0; f < 8; f++) {
        int n = (kgrp << 6) + ((f >> 1) << 4) + ((f & 1) << 3) + ((lane & 3) << 1);
        {
            float vx = acc[f].x, vy = acc[f].y;
            uint32_t h = bfpack(vx, vy);
            __nv_bfloat162* hp = (__nv_bfloat162*)&h;
            uint32_t l = bfpack(vx - __bfloat162float(hp->x),
                                vy - __bfloat162float(hp->y));
            *(uint32_t*)&g_PH[prow + n] = h;
            *(uint32_t*)&g_PL[prow + n] = l;
        }
        {
            float vx = acc[f].z, vy = acc[f].w;
            uint32_t h = bfpack(vx, vy);
            __nv_bfloat162* hp = (__nv_bfloat162*)&h;
            uint32_t l = bfpack(vx - __bfloat162float(hp->x),
                                vy - __bfloat162float(hp->y));
            *(uint32_t*)&g_PH[prow + 8 * Nn + n] = h;
            *(uint32_t*)&g_PL[prow + 8 * Nn + n] = l;
        }
    }
}

// ---------------- K3: Et = exp(P^T theta), bf16 hi/lo out, Z sums -----------
// grid (8 ktile, 8 ntile, 32 b), block 256. CTA tile 128k x 128n, c = 64.
__global__ __launch_bounds__(256, 2) void k3_att_mma(void) {
    extern __shared__ __align__(16) char sm3[];
    __nv_bfloat16* sPh = (__nv_bfloat16*)sm3;              // [64][136]
    __nv_bfloat16* sPl = (__nv_bfloat16*)(sm3 + 17408);
    __nv_bfloat16* sTh = (__nv_bfloat16*)(sm3 + 34816);
    __nv_bfloat16* sTl = (__nv_bfloat16*)(sm3 + 52224);
    int b = blockIdx.z, k0 = blockIdx.x << 7, n0 = blockIdx.y << 7;
    int t = threadIdx.x, w = t >> 5, lane = t & 31;
    int kw = w & 3, nw = w >> 2;

#pragma unroll
    for (int i = 0; i < 4; i++) {
        int lin = t + (i << 8);
        int r = lin >> 4, q = lin & 15;
        size_t pofs = ((size_t)(b << 6) + r) * Nn + k0 + (q << 3);
        size_t tofs = ((size_t)(b << 6) + r) * Nn + n0 + (q << 3);
        *(uint4*)&sPh[r * 136 + (q << 3)] = *(const uint4*)&g_PH[pofs];
        *(uint4*)&sPl[r * 136 + (q << 3)] = *(const uint4*)&g_PL[pofs];
        *(uint4*)&sTh[r * 136 + (q << 3)] = *(const uint4*)&g_thH[tofs];
        *(uint4*)&sTl[r * 136 + (q << 3)] = *(const uint4*)&g_thL[tofs];
    }
    __syncthreads();

    float4 acc[2][8] = {};
    int bq = lane >> 3, br = lane & 7;
#pragma unroll
    for (int kk = 0; kk < 4; kk++) {
        int c0 = kk << 4;
        uint32_t ah[2][4], al[2][4];
#pragma unroll
        for (int mt = 0; mt < 2; mt++) {
            int m0 = (kw << 5) + (mt << 4);
            int rowc = c0 + ((bq >> 1) << 3) + br;
            int colm = m0 + ((bq & 1) << 3);
            ldsm_x4t(smem_u32(&sPh[rowc * 136 + colm]), ah[mt]);
            ldsm_x4t(smem_u32(&sPl[rowc * 136 + colm]), al[mt]);
        }
#pragma unroll
        for (int j = 0; j < 4; j++) {
            int rowc = c0 + ((bq & 1) << 3) + br;
            int coln = (nw << 6) + (j << 4) + ((bq >> 1) << 3);
            uint32_t bh[4], bl[4];
            ldsm_x4t(smem_u32(&sTh[rowc * 136 + coln]), bh);
            ldsm_x4t(smem_u32(&sTl[rowc * 136 + coln]), bl);
#pragma unroll
            for (int mt = 0; mt < 2; mt++) {
                mma_bf16(acc[mt][j * 2], ah[mt], bh[0], bh[1]);
                mma_bf16(acc[mt][j * 2 + 1], ah[mt], bh[2], bh[3]);
                mma_bf16(acc[mt][j * 2], al[mt], bh[0], bh[1]);
                mma_bf16(acc[mt][j * 2 + 1], al[mt], bh[2], bh[3]);
                mma_bf16(acc[mt][j * 2], ah[mt], bl[0], bl[1]);
                mma_bf16(acc[mt][j * 2 + 1], ah[mt], bl[2], bl[3]);
            }
        }
    }

    __syncthreads();
    __nv_bfloat16* sEH = (__nv_bfloat16*)sm3;
    __nv_bfloat16* sEL = (__nv_bfloat16*)(sm3 + 34816);
#pragma unroll
    for (int mt = 0; mt < 2; mt++) {
        int krow = (kw << 5) + (mt << 4) + (lane >> 2);
        float sA = 0.f, sB = 0.f;
#pragma unroll
        for (int j = 0; j < 8; j++) {
            int nc = (nw << 6) + (j << 3) + ((lane & 3) << 1);
            float ex = __expf(acc[mt][j].x), ey = __expf(acc[mt][j].y);
            float ez = __expf(acc[mt][j].z), ew = __expf(acc[mt][j].w);
            sA += ex + ey; sB += ez + ew;
            uint32_t h0 = bfpack(ex, ey);
            __nv_bfloat162* hp = (__nv_bfloat162*)&h0;
            uint32_t l0 = bfpack(ex - __bfloat162float(hp->x),
                                 ey - __bfloat162float(hp->y));
            *(uint32_t*)&sEH[krow * 136 + nc] = h0;
            *(uint32_t*)&sEL[krow * 136 + nc] = l0;
            uint32_t h1 = bfpack(ez, ew);
            __nv_bfloat162* hq = (__nv_bfloat162*)&h1;
            uint32_t l1 = bfpack(ez - __bfloat162float(hq->x),
                                 ew - __bfloat162float(hq->y));
            *(uint32_t*)&sEH[(krow + 8) * 136 + nc] = h1;
            *(uint32_t*)&sEL[(krow + 8) * 136 + nc] = l1;
        }
        sA += __shfl_xor_sync(0xffffffffu, sA, 1);
        sA += __shfl_xor_sync(0xffffffffu, sA, 2);
        sB += __shfl_xor_sync(0xffffffffu, sB, 1);
        sB += __shfl_xor_sync(0xffffffffu, sB, 2);
        if ((lane & 3) == 0) {
            atomicAdd(&g_Z[b * Nn + k0 + krow], sA);
            atomicAdd(&g_Z[b * Nn + k0 + krow + 8], sB);
        }
    }
    __syncthreads();
#pragma unroll
    for (int i = 0; i < 8; i++) {
        int lin = t + (i << 8);
        int r = lin >> 4, q = lin & 15;
        size_t off = ((size_t)(b * Nn + k0 + r)) * Nn + n0 + (q << 3);
        *(uint4*)&g_EH[off] = *(uint4*)&sEH[r * 136 + (q << 3)];
        *(uint4*)&g_EL[off] = *(uint4*)&sEL[r * 136 + (q << 3)];
    }
}

// ---------------- K5: gz = (wmask@gm)/Z, bf16 hi/lo out ---------------------
__global__ __launch_bounds__(256) void k5_gmz(const float* __restrict__ wmask) {
    __shared__ __align__(16) float smG[64][68];
    __shared__ __align__(16) float smW[64][68];
    __shared__ float sz[64];
    int b = blockIdx.x, m0 = blockIdx.y << 6;
    int t = threadIdx.x;
    const float* gm = g_gm + (b << 6) * Nn;
#pragma unroll
    for (int i = 0; i < 4; i++) {
        int idx = t + (i << 8);
        int r = idx >> 4, c4 = idx & 15;
        *(float4*)&smG[r][c4 << 2] = *(const float4*)&gm[r * Nn + m0 + (c4 << 2)];
        *(float4*)&smW[r][c4 << 2] = *(const float4*)&wmask[r * 64 + (c4 << 2)];
    }
    if (t < 64) sz[t] = 1.0f / g_Z[b * Nn + m0 + t];
    __syncthreads();
    int m = t & 63, og = t >> 6;
    float inv = sz[m];
#pragma unroll
    for (int q = 0; q < 16; q++) {
        int o = (og << 4) + q;
        float s = 0.0f;
#pragma unroll
        for (int c = 0; c < 64; c++) s += smW[o][c] * smG[c][m];
        float v = s * inv;
        size_t idx = ((size_t)(b << 6) + o) * Nn + m0 + m;
        __nv_bfloat16 h = __float2bfloat16(v);
        g_gzH[idx] = h;
        g_gzL[idx] = __float2bfloat16(v - __bfloat162float(h));
    }
}

// ---------------- K4: out[o][n] = sum_m gz[o][m] E[m][n] + x (cp.async pipe)
// grid (32 b, 8 ntile), block 256. Warp tile 16o x 64n, chunk 64, 2 bufs.
// Buffer layout (bytes, per buf=53248): aH 0, aL 9216, bH 18432, bL 35840.
// A stride 144B, B stride 272B (136 bf16).
__global__ __launch_bounds__(256, 2) void k4_out_mma(
    const float* __restrict__ x, float* __restrict__ out) {
    extern __shared__ __align__(16) char sm4[];
    uint32_t sb = smem_u32(sm4);
    int b = blockIdx.x, n0 = blockIdx.y << 7;
    int t = threadIdx.x, w = t >> 5, lane = t & 31;
    int ogrp = w & 3, ngrp = w >> 2;

    float4 acc[8] = {};
    int lr = lane & 15, lh = lane >> 4;
    int bq = lane >> 3, br = lane & 7;

    auto stage = [&](int mc, int buf) {
        uint32_t base = sb + buf * 53248u;
        uint32_t aH = base, aL = base + 9216u, bH = base + 18432u, bL = base + 35840u;
#pragma unroll
        for (int i = 0; i < 2; i++) {
            int lin = t + (i << 8);
            int r = lin >> 3, q = lin & 7;
            size_t gofs = ((size_t)(b << 6) + r) * Nn + mc + (q << 3);
            cpa16(aH + r * 144 + (q << 4), &g_gzH[gofs]);
            cpa16(aL + r * 144 + (q << 4), &g_gzL[gofs]);
        }
#pragma unroll
        for (int i = 0; i < 4; i++) {
            int lin = t + (i << 8);
            int r = lin >> 4, q = lin & 15;
            size_t off = ((size_t)(b * Nn) + mc + r) * Nn + n0 + (q << 3);
            cpa16(bH + r * 272 + (q << 4), &g_EH[off]);
            cpa16(bL + r * 272 + (q << 4), &g_EL[off]);
        }
        CPA_COMMIT();
    };

    stage(0, 0);
    for (int ci = 0; ci < 16; ci++) {
        int buf = ci & 1;
        if (ci + 1 < 16) { stage((ci + 1) << 6, buf ^ 1); CPA_WAIT(1); }
        else { CPA_WAIT(0); }
        __syncthreads();
        uint32_t base = sb + buf * 53248u;
        uint32_t aH = base, aL = base + 9216u, bH = base + 18432u, bL = base + 35840u;
#pragma unroll
        for (int kk = 0; kk < 4; kk++) {
            uint32_t ah[4], al[4];
            uint32_t arow = (ogrp * 16 + lr) * 144 + kk * 32 + lh * 16;
            ldsm_x4(aH + arow, ah);
            ldsm_x4(aL + arow, al);
#pragma unroll
            for (int j = 0; j < 4; j++) {
                int rowm = (kk << 4) + ((bq & 1) << 3) + br;
                int coln = (ngrp << 6) + (j << 4) + ((bq >> 1) << 3);
                uint32_t boff = rowm * 272 + coln * 2;
                uint32_t bh[4], bl[4];
                ldsm_x4t(bH + boff, bh);
                mma_bf16(acc[j * 2], ah, bh[0], bh[1]);
                mma_bf16(acc[j * 2 + 1], ah, bh[2], bh[3]);
                mma_bf16(acc[j * 2], al, bh[0], bh[1]);
                mma_bf16(acc[j * 2 + 1], al, bh[2], bh[3]);
                ldsm_x4t(bL + boff, bl);
                mma_bf16(acc[j * 2], ah, bl[0], bl[1]);
                mma_bf16(acc[j * 2 + 1], ah, bl[2], bl[3]);
            }
        }
        __syncthreads();
    }
    int o = (ogrp << 4) + (lane >> 2);
#pragma unroll
    for (int f = 0; f < 8; f++) {
        int n = n0 + (ngrp << 6) + ((f >> 1) << 4) + ((f & 1) << 3) + ((lane & 3) << 1);
        size_t off = ((size_t)(b << 6) + o) * Nn + n;
        float2 xv = *(const float2*)&x[off];
        *(float2*)&out[off] = make_float2(acc[f].x + xv.x, acc[f].y + xv.y);
        size_t off2 = off + (size_t)8 * Nn;
        float2 xv2 = *(const float2*)&x[off2];
        *(float2*)&out[off2] = make_float2(acc[f].z + xv2.x, acc[f].w + xv2.y);
    }
}

// ---------------- launch ----------------------------------------------------
extern "C" void kernel_launch(void* const* d_in, const int* in_sizes, int n_in,
                              void* d_out, int out_size) {
    const float* x      = (const float*)d_in[0];
    const float* wphi   = (const float*)d_in[1];
    const float* wtheta = (const float*)d_in[2];
    const float* wg     = (const float*)d_in[3];
    const float* wmask  = (const float*)d_in[4];
    const float* wmv    = (const float*)d_in[5];
    const float* wmk    = (const float*)d_in[6];
    float* out = (float*)d_out;

    cudaFuncSetAttribute(k2_P_mma, cudaFuncAttributeMaxDynamicSharedMemorySize, 110592);
    cudaFuncSetAttribute(k3_att_mma, cudaFuncAttributeMaxDynamicSharedMemorySize, 69632);
    cudaFuncSetAttribute(k4_out_mma, cudaFuncAttributeMaxDynamicSharedMemorySize, 106496);

    k0_prep<<<128, 256>>>(wmv, wg);
    k0w_split<<<1024, 256>>>(wmk);
    k1_channel<<<dim3(32, 16), 256>>>(x, wphi, wtheta);
    k2_P_mma<<<dim3(32, 8), 256, 110592>>>();
    k3_att_mma<<<dim3(8, 8, 32), 256, 69632>>>();
    k5_gmz<<<dim3(32, 16), 256>>>(wmask);
    k4_out_mma<<<dim3(32, 8), 256, 106496>>>(x, out);
}

// round 9
// speedup vs baseline: 2.0127x; 1.0909x over previous
#include <cuda_runtime.h>
#include <cuda_bf16.h>
#include <cstdint>

#define Bq 32
#define Cc 64
#define Nn 1024

// ---------------- scratch (device globals) ----------------------------------
__device__ __nv_bfloat16 g_phiH[Bq * Cc * Nn];  // [b][c][m]
__device__ __nv_bfloat16 g_phiL[Bq * Cc * Nn];
__device__ __nv_bfloat16 g_wmkH[Nn * Nn];       // [k][m]
__device__ __nv_bfloat16 g_wmkL[Nn * Nn];
__device__ __nv_bfloat16 g_thH[Bq * Cc * Nn];   // [b][c][n] theta hi/lo
__device__ __nv_bfloat16 g_thL[Bq * Cc * Nn];
__device__ __nv_bfloat16 g_PH[Bq * Cc * Nn];    // [b][c][k] P hi/lo
__device__ __nv_bfloat16 g_PL[Bq * Cc * Nn];
__device__ float g_gm[Bq * Cc * Nn];            // [b][c][n]
__device__ __nv_bfloat16 g_EH[(size_t)Bq * Nn * Nn];  // [b][k][n] exp hi (64MB)
__device__ __nv_bfloat16 g_EL[(size_t)Bq * Nn * Nn];  // [b][k][n] exp lo (64MB)
__device__ float g_Z[Bq * Nn];
__device__ __nv_bfloat16 g_gzH[Bq * Cc * Nn];   // [b][o][m] (w_mask@gm)/Z hi/lo
__device__ __nv_bfloat16 g_gzL[Bq * Cc * Nn];
// small weight splits (filled by k0)
__device__ __nv_bfloat16 g_wphiH[Cc * Cc], g_wphiL[Cc * Cc];
__device__ __nv_bfloat16 g_wthH[Cc * Cc],  g_wthL[Cc * Cc];
__device__ __nv_bfloat16 g_wgvH[Cc * Cc],  g_wgvL[Cc * Cc];
__device__ __nv_bfloat16 g_wmaskH[Cc * Cc], g_wmaskL[Cc * Cc];

// ---------------- mma.sync / cp.async helpers -------------------------------
__device__ __forceinline__ uint32_t smem_u32(const void* p) {
    uint32_t a;
    asm("{ .reg .u64 t; cvta.to.shared.u64 t, %1; cvt.u32.u64 %0, t; }"
        : "=r"(a) : "l"(p));
    return a;
}
__device__ __forceinline__ void ldsm_x4(uint32_t addr, uint32_t r[4]) {
    asm volatile("ldmatrix.sync.aligned.m8n8.x4.shared.b16 {%0,%1,%2,%3}, [%4];"
                 : "=r"(r[0]), "=r"(r[1]), "=r"(r[2]), "=r"(r[3]) : "r"(addr));
}
__device__ __forceinline__ void ldsm_x4t(uint32_t addr, uint32_t r[4]) {
    asm volatile("ldmatrix.sync.aligned.m8n8.x4.trans.shared.b16 {%0,%1,%2,%3}, [%4];"
                 : "=r"(r[0]), "=r"(r[1]), "=r"(r[2]), "=r"(r[3]) : "r"(addr));
}
__device__ __forceinline__ void mma_bf16(float4& d, const uint32_t a[4],
                                         uint32_t b0, uint32_t b1) {
    asm volatile(
        "mma.sync.aligned.m16n8k16.row.col.f32.bf16.bf16.f32 "
        "{%0,%1,%2,%3}, {%4,%5,%6,%7}, {%8,%9}, {%0,%1,%2,%3};"
        : "+f"(d.x), "+f"(d.y), "+f"(d.z), "+f"(d.w)
        : "r"(a[0]), "r"(a[1]), "r"(a[2]), "r"(a[3]), "r"(b0), "r"(b1));
}
__device__ __forceinline__ void cpa16(uint32_t s, const void* g) {
    asm volatile("cp.async.cg.shared.global [%0], [%1], 16;" :: "r"(s), "l"(g));
}
#define CPA_COMMIT() asm volatile("cp.async.commit_group;" ::: "memory")
#define CPA_WAIT(n) asm volatile("cp.async.wait_group %0;" :: "n"(n) : "memory")

__device__ __forceinline__ uint32_t bfpack(float a, float b) {
    __nv_bfloat162 h;
    h.x = __float2bfloat16(a); h.y = __float2bfloat16(b);
    return *(uint32_t*)&h;
}
__device__ __forceinline__ void split4(float4 v, uint2& hi, uint2& lo) {
    uint32_t hA = bfpack(v.x, v.y), hB = bfpack(v.z, v.w);
    __nv_bfloat162* hp = (__nv_bfloat162*)&hA;
    __nv_bfloat162* hq = (__nv_bfloat162*)&hB;
    uint32_t lA = bfpack(v.x - __bfloat162float(hp->x), v.y - __bfloat162float(hp->y));
    uint32_t lB = bfpack(v.z - __bfloat162float(hq->x), v.w - __bfloat162float(hq->y));
    hi = make_uint2(hA, hB); lo = make_uint2(lA, lB);
}
__device__ __forceinline__ void split2(float a, float b, uint32_t& h, uint32_t& l) {
    h = bfpack(a, b);
    __nv_bfloat162* hp = (__nv_bfloat162*)&h;
    l = bfpack(a - __bfloat162float(hp->x), b - __bfloat162float(hp->y));
}

// ---------------- K0: zero Z, wgv = w_mv @ w_g, split small weights ---------
__global__ void k0_prep(const float* __restrict__ wmv, const float* __restrict__ wg,
                        const float* __restrict__ wphi, const float* __restrict__ wtheta,
                        const float* __restrict__ wmask) {
    int t = blockIdx.x * blockDim.x + threadIdx.x;
    if (t < Bq * Nn) g_Z[t] = 0.0f;
    if (t < Cc * Cc) {
        int d = t >> 6, ci = t & 63;
        float s = 0.0f;
#pragma unroll
        for (int c = 0; c < 64; c++) s += wmv[d * 64 + c] * wg[c * 64 + ci];
        __nv_bfloat16 h;
        h = __float2bfloat16(s);
        g_wgvH[t] = h; g_wgvL[t] = __float2bfloat16(s - __bfloat162float(h));
        float v = wphi[t];
        h = __float2bfloat16(v);
        g_wphiH[t] = h; g_wphiL[t] = __float2bfloat16(v - __bfloat162float(h));
        v = wtheta[t];
        h = __float2bfloat16(v);
        g_wthH[t] = h; g_wthL[t] = __float2bfloat16(v - __bfloat162float(h));
        v = wmask[t];
        h = __float2bfloat16(v);
        g_wmaskH[t] = h; g_wmaskL[t] = __float2bfloat16(v - __bfloat162float(h));
    }
}

// ---------------- K0w: split wmk into bf16 hi/lo ----------------------------
__global__ __launch_bounds__(256) void k0w_split(const float* __restrict__ wmk) {
    int i = blockIdx.x * 256 + threadIdx.x;
    float4 v = ((const float4*)wmk)[i];
    uint2 hi, lo;
    split4(v, hi, lo);
    ((uint2*)g_wmkH)[i] = hi;
    ((uint2*)g_wmkL)[i] = lo;
}

// ---------------- K1: channel GEMMs via mma.sync (phi, theta, gm) -----------
// grid (32 b, 8 ntile), block 256 = 8 warps. CTA tile 64c x 128n, red ci=64.
// smem: sXh[64][136]@0, sXl@17408, then 6 weight arrays [64][72] (9216 B each)
// order: wphiH@34816, wphiL@44032, wthH@53248, wthL@62464, wgvH@71680, wgvL@80896.
__global__ __launch_bounds__(256, 2) void k1_mma(const float* __restrict__ x) {
    extern __shared__ __align__(16) char sm1[];
    __nv_bfloat16* sXh = (__nv_bfloat16*)sm1;
    __nv_bfloat16* sXl = (__nv_bfloat16*)(sm1 + 17408);
    __nv_bfloat16* sW[6] = {
        (__nv_bfloat16*)(sm1 + 34816), (__nv_bfloat16*)(sm1 + 44032),
        (__nv_bfloat16*)(sm1 + 53248), (__nv_bfloat16*)(sm1 + 62464),
        (__nv_bfloat16*)(sm1 + 71680), (__nv_bfloat16*)(sm1 + 80896)};
    int b = blockIdx.x, n0 = blockIdx.y << 7;
    int t = threadIdx.x, w = t >> 5, lane = t & 31;
    int cgrp = w & 3, ngrp = w >> 2;

    // stage x tile [64 ci][128 n] fp32 -> hi/lo
#pragma unroll
    for (int i = 0; i < 8; i++) {
        int lin = t + (i << 8);
        int r = lin >> 5, q = lin & 31;
        float4 v = *(const float4*)&x[((size_t)(b << 6) + r) * Nn + n0 + (q << 2)];
        uint2 hi, lo;
        split4(v, hi, lo);
        *(uint2*)&sXh[r * 136 + (q << 2)] = hi;
        *(uint2*)&sXl[r * 136 + (q << 2)] = lo;
    }
    // stage 6 weight arrays (pre-split)
    {
        const __nv_bfloat16* src[6] = {g_wphiH, g_wphiL, g_wthH, g_wthL, g_wgvH, g_wgvL};
#pragma unroll
        for (int a = 0; a < 6; a++)
#pragma unroll
            for (int i = 0; i < 2; i++) {
                int lin = t + (i << 8);
                int r = lin >> 3, q = lin & 7;
                *(uint4*)&sW[a][r * 72 + (q << 3)] = *(const uint4*)&src[a][r * 64 + (q << 3)];
            }
    }
    __syncthreads();

    int lr = lane & 15, lh = lane >> 4;
    int bq = lane >> 3, br = lane & 7;

#pragma unroll
    for (int p = 0; p < 3; p++) {
        float4 acc[8] = {};
        __nv_bfloat16* WH = sW[p * 2];
        __nv_bfloat16* WL = sW[p * 2 + 1];
#pragma unroll
        for (int kk = 0; kk < 4; kk++) {
            uint32_t ah[4], al[4];
            ldsm_x4(smem_u32(&WH[(cgrp * 16 + lr) * 72 + kk * 16 + lh * 8]), ah);
            ldsm_x4(smem_u32(&WL[(cgrp * 16 + lr) * 72 + kk * 16 + lh * 8]), al);
#pragma unroll
            for (int j = 0; j < 4; j++) {
                int rowk = (kk << 4) + ((bq & 1) << 3) + br;
                int coln = (ngrp << 6) + (j << 4) + ((bq >> 1) << 3);
                uint32_t bh[4], bl[4];
                ldsm_x4t(smem_u32(&sXh[rowk * 136 + coln]), bh);
                mma_bf16(acc[j * 2], ah, bh[0], bh[1]);
                mma_bf16(acc[j * 2 + 1], ah, bh[2], bh[3]);
                mma_bf16(acc[j * 2], al, bh[0], bh[1]);
                mma_bf16(acc[j * 2 + 1], al, bh[2], bh[3]);
                ldsm_x4t(smem_u32(&sXl[rowk * 136 + coln]), bl);
                mma_bf16(acc[j * 2], ah, bl[0], bl[1]);
                mma_bf16(acc[j * 2 + 1], ah, bl[2], bl[3]);
            }
        }
        // epilogue
        int m = (cgrp << 4) + (lane >> 2);
        if (p == 2) {
            float* O = g_gm + (size_t)(b << 6) * Nn;
#pragma unroll
            for (int f = 0; f < 8; f++) {
                int n = n0 + (ngrp << 6) + ((f >> 1) << 4) + ((f & 1) << 3) + ((lane & 3) << 1);
                *(float2*)&O[(size_t)m * Nn + n] = make_float2(acc[f].x, acc[f].y);
                *(float2*)&O[(size_t)(m + 8) * Nn + n] = make_float2(acc[f].z, acc[f].w);
            }
        } else {
            __nv_bfloat16* H = (p == 0 ? g_phiH : g_thH);
            __nv_bfloat16* L = (p == 0 ? g_phiL : g_thL);
            size_t rowa = ((size_t)(b << 6) + m) * Nn;
            size_t rowb2 = ((size_t)(b << 6) + m + 8) * Nn;
#pragma unroll
            for (int f = 0; f < 8; f++) {
                int n = n0 + (ngrp << 6) + ((f >> 1) << 4) + ((f & 1) << 3) + ((lane & 3) << 1);
                uint32_t h, l;
                split2(acc[f].x, acc[f].y, h, l);
                *(uint32_t*)&H[rowa + n] = h;
                *(uint32_t*)&L[rowa + n] = l;
                split2(acc[f].z, acc[f].w, h, l);
                *(uint32_t*)&H[rowb2 + n] = h;
                *(uint32_t*)&L[rowb2 + n] = l;
            }
        }
    }
}

// ---------------- K2: P = phi @ wmk^T  (mma.sync bf16x3, cp.async pipe) -----
__global__ __launch_bounds__(256, 2) void k2_P_mma(void) {
    extern __shared__ __align__(16) char sm2[];
    uint32_t sb = smem_u32(sm2);
    int b = blockIdx.x, k0 = blockIdx.y << 7;
    int t = threadIdx.x, w = t >> 5, lane = t & 31;
    int cgrp = w & 3, kgrp = w >> 2;

    const __nv_bfloat16* Ah = g_phiH + (size_t)(b << 6) * Nn;
    const __nv_bfloat16* Al = g_phiL + (size_t)(b << 6) * Nn;

    float4 acc[8] = {};
    int lr = lane & 15, lh = lane >> 4;
    int bq = lane >> 3, br = lane & 7;

    auto stage = [&](int mc, int buf) {
        uint32_t base = sb + buf * 55296u;
        uint32_t aH = base, aL = base + 9216u, bH = base + 18432u, bL = base + 36864u;
#pragma unroll
        for (int i = 0; i < 2; i++) {
            int lin = t + (i << 8);
            int r = lin >> 3, q = lin & 7;
            cpa16(aH + r * 144 + (q << 4), &Ah[(size_t)r * Nn + mc + (q << 3)]);
            cpa16(aL + r * 144 + (q << 4), &Al[(size_t)r * Nn + mc + (q << 3)]);
        }
#pragma unroll
        for (int i = 0; i < 4; i++) {
            int lin = t + (i << 8);
            int r = lin >> 3, q = lin & 7;
            cpa16(bH + r * 144 + (q << 4), &g_wmkH[(size_t)(k0 + r) * Nn + mc + (q << 3)]);
            cpa16(bL + r * 144 + (q << 4), &g_wmkL[(size_t)(k0 + r) * Nn + mc + (q << 3)]);
        }
        CPA_COMMIT();
    };

    stage(0, 0);
    for (int ci = 0; ci < 16; ci++) {
        int buf = ci & 1;
        if (ci + 1 < 16) { stage((ci + 1) << 6, buf ^ 1); CPA_WAIT(1); }
        else { CPA_WAIT(0); }
        __syncthreads();
        uint32_t base = sb + buf * 55296u;
        uint32_t aH = base, aL = base + 9216u, bH = base + 18432u, bL = base + 36864u;
#pragma unroll
        for (int kk = 0; kk < 4; kk++) {
            uint32_t ah[4], al[4];
            uint32_t arow = (cgrp * 16 + lr) * 144 + kk * 32 + lh * 16;
            ldsm_x4(aH + arow, ah);
            ldsm_x4(aL + arow, al);
#pragma unroll
            for (int j = 0; j < 4; j++) {
                int rowb = (kgrp << 6) + (j << 4) + ((bq >> 1) << 3) + br;
                uint32_t boff = rowb * 144 + kk * 32 + ((bq & 1) << 4);
                uint32_t bh[4], bl[4];
                ldsm_x4(bH + boff, bh);
                mma_bf16(acc[j * 2], ah, bh[0], bh[1]);
                mma_bf16(acc[j * 2 + 1], ah, bh[2], bh[3]);
                mma_bf16(acc[j * 2], al, bh[0], bh[1]);
                mma_bf16(acc[j * 2 + 1], al, bh[2], bh[3]);
                ldsm_x4(bL + boff, bl);
                mma_bf16(acc[j * 2], ah, bl[0], bl[1]);
                mma_bf16(acc[j * 2 + 1], ah, bl[2], bl[3]);
            }
        }
        __syncthreads();
    }

    int m = (cgrp << 4) + (lane >> 2);
    size_t prow = ((size_t)(b << 6) + m) * Nn + k0;
#pragma unroll
    for (int f = 0; f < 8; f++) {
        int n = (kgrp << 6) + ((f >> 1) << 4) + ((f & 1) << 3) + ((lane & 3) << 1);
        uint32_t h, l;
        split2(acc[f].x, acc[f].y, h, l);
        *(uint32_t*)&g_PH[prow + n] = h;
        *(uint32_t*)&g_PL[prow + n] = l;
        split2(acc[f].z, acc[f].w, h, l);
        *(uint32_t*)&g_PH[prow + 8 * Nn + n] = h;
        *(uint32_t*)&g_PL[prow + 8 * Nn + n] = l;
    }
}

// ---------------- K3: Et = exp(P^T theta), bf16 hi/lo out, Z sums -----------
__global__ __launch_bounds__(256, 2) void k3_att_mma(void) {
    extern __shared__ __align__(16) char sm3[];
    __nv_bfloat16* sPh = (__nv_bfloat16*)sm3;              // [64][136]
    __nv_bfloat16* sPl = (__nv_bfloat16*)(sm3 + 17408);
    __nv_bfloat16* sTh = (__nv_bfloat16*)(sm3 + 34816);
    __nv_bfloat16* sTl = (__nv_bfloat16*)(sm3 + 52224);
    int b = blockIdx.z, k0 = blockIdx.x << 7, n0 = blockIdx.y << 7;
    int t = threadIdx.x, w = t >> 5, lane = t & 31;
    int kw = w & 3, nw = w >> 2;

#pragma unroll
    for (int i = 0; i < 4; i++) {
        int lin = t + (i << 8);
        int r = lin >> 4, q = lin & 15;
        size_t pofs = ((size_t)(b << 6) + r) * Nn + k0 + (q << 3);
        size_t tofs = ((size_t)(b << 6) + r) * Nn + n0 + (q << 3);
        *(uint4*)&sPh[r * 136 + (q << 3)] = *(const uint4*)&g_PH[pofs];
        *(uint4*)&sPl[r * 136 + (q << 3)] = *(const uint4*)&g_PL[pofs];
        *(uint4*)&sTh[r * 136 + (q << 3)] = *(const uint4*)&g_thH[tofs];
        *(uint4*)&sTl[r * 136 + (q << 3)] = *(const uint4*)&g_thL[tofs];
    }
    __syncthreads();

    float4 acc[2][8] = {};
    int bq = lane >> 3, br = lane & 7;
#pragma unroll
    for (int kk = 0; kk < 4; kk++) {
        int c0 = kk << 4;
        uint32_t ah[2][4], al[2][4];
#pragma unroll
        for (int mt = 0; mt < 2; mt++) {
            int m0 = (kw << 5) + (mt << 4);
            int rowc = c0 + ((bq >> 1) << 3) + br;
            int colm = m0 + ((bq & 1) << 3);
            ldsm_x4t(smem_u32(&sPh[rowc * 136 + colm]), ah[mt]);
            ldsm_x4t(smem_u32(&sPl[rowc * 136 + colm]), al[mt]);
        }
#pragma unroll
        for (int j = 0; j < 4; j++) {
            int rowc = c0 + ((bq & 1) << 3) + br;
            int coln = (nw << 6) + (j << 4) + ((bq >> 1) << 3);
            uint32_t bh[4], bl[4];
            ldsm_x4t(smem_u32(&sTh[rowc * 136 + coln]), bh);
            ldsm_x4t(smem_u32(&sTl[rowc * 136 + coln]), bl);
#pragma unroll
            for (int mt = 0; mt < 2; mt++) {
                mma_bf16(acc[mt][j * 2], ah[mt], bh[0], bh[1]);
                mma_bf16(acc[mt][j * 2 + 1], ah[mt], bh[2], bh[3]);
                mma_bf16(acc[mt][j * 2], al[mt], bh[0], bh[1]);
                mma_bf16(acc[mt][j * 2 + 1], al[mt], bh[2], bh[3]);
                mma_bf16(acc[mt][j * 2], ah[mt], bl[0], bl[1]);
                mma_bf16(acc[mt][j * 2 + 1], ah[mt], bl[2], bl[3]);
            }
        }
    }

    __syncthreads();
    __nv_bfloat16* sEH = (__nv_bfloat16*)sm3;
    __nv_bfloat16* sEL = (__nv_bfloat16*)(sm3 + 34816);
#pragma unroll
    for (int mt = 0; mt < 2; mt++) {
        int krow = (kw << 5) + (mt << 4) + (lane >> 2);
        float sA = 0.f, sB = 0.f;
#pragma unroll
        for (int j = 0; j < 8; j++) {
            int nc = (nw << 6) + (j << 3) + ((lane & 3) << 1);
            float ex = __expf(acc[mt][j].x), ey = __expf(acc[mt][j].y);
            float ez = __expf(acc[mt][j].z), ew = __expf(acc[mt][j].w);
            sA += ex + ey; sB += ez + ew;
            uint32_t h0, l0, h1, l1;
            split2(ex, ey, h0, l0);
            split2(ez, ew, h1, l1);
            *(uint32_t*)&sEH[krow * 136 + nc] = h0;
            *(uint32_t*)&sEL[krow * 136 + nc] = l0;
            *(uint32_t*)&sEH[(krow + 8) * 136 + nc] = h1;
            *(uint32_t*)&sEL[(krow + 8) * 136 + nc] = l1;
        }
        sA += __shfl_xor_sync(0xffffffffu, sA, 1);
        sA += __shfl_xor_sync(0xffffffffu, sA, 2);
        sB += __shfl_xor_sync(0xffffffffu, sB, 1);
        sB += __shfl_xor_sync(0xffffffffu, sB, 2);
        if ((lane & 3) == 0) {
            atomicAdd(&g_Z[b * Nn + k0 + krow], sA);
            atomicAdd(&g_Z[b * Nn + k0 + krow + 8], sB);
        }
    }
    __syncthreads();
#pragma unroll
    for (int i = 0; i < 8; i++) {
        int lin = t + (i << 8);
        int r = lin >> 4, q = lin & 15;
        size_t off = ((size_t)(b * Nn + k0 + r)) * Nn + n0 + (q << 3);
        *(uint4*)&g_EH[off] = *(uint4*)&sEH[r * 136 + (q << 3)];
        *(uint4*)&g_EL[off] = *(uint4*)&sEL[r * 136 + (q << 3)];
    }
}

// ---------------- K5: gz = (wmask@gm)/Z via mma.sync, bf16 hi/lo out --------
// grid (32 b, 8 mtile), block 256. CTA tile 64o x 128m, red c=64.
// smem: sGh[64][136]@0, sGl@17408, sWh[64][72]@34816, sWl@44032, szm[128]@53248.
__global__ __launch_bounds__(256, 2) void k5_gmz_mma(void) {
    extern __shared__ __align__(16) char sm5[];
    __nv_bfloat16* sGh = (__nv_bfloat16*)sm5;
    __nv_bfloat16* sGl = (__nv_bfloat16*)(sm5 + 17408);
    __nv_bfloat16* sWh = (__nv_bfloat16*)(sm5 + 34816);
    __nv_bfloat16* sWl = (__nv_bfloat16*)(sm5 + 44032);
    float* szm = (float*)(sm5 + 53248);
    int b = blockIdx.x, m0 = blockIdx.y << 7;
    int t = threadIdx.x, w = t >> 5, lane = t & 31;
    int ogrp = w & 3, mgrp = w >> 2;

    const float* gm = g_gm + (size_t)(b << 6) * Nn;
#pragma unroll
    for (int i = 0; i < 8; i++) {
        int lin = t + (i << 8);
        int r = lin >> 5, q = lin & 31;
        float4 v = *(const float4*)&gm[(size_t)r * Nn + m0 + (q << 2)];
        uint2 hi, lo;
        split4(v, hi, lo);
        *(uint2*)&sGh[r * 136 + (q << 2)] = hi;
        *(uint2*)&sGl[r * 136 + (q << 2)] = lo;
    }
#pragma unroll
    for (int i = 0; i < 2; i++) {
        int lin = t + (i << 8);
        int r = lin >> 3, q = lin & 7;
        *(uint4*)&sWh[r * 72 + (q << 3)] = *(const uint4*)&g_wmaskH[r * 64 + (q << 3)];
        *(uint4*)&sWl[r * 72 + (q << 3)] = *(const uint4*)&g_wmaskL[r * 64 + (q << 3)];
    }
    if (t < 128) szm[t] = 1.0f / g_Z[b * Nn + m0 + t];
    __syncthreads();

    int lr = lane & 15, lh = lane >> 4;
    int bq = lane >> 3, br = lane & 7;

    float4 acc[8] = {};
#pragma unroll
    for (int kk = 0; kk < 4; kk++) {
        uint32_t ah[4], al[4];
        ldsm_x4(smem_u32(&sWh[(ogrp * 16 + lr) * 72 + kk * 16 + lh * 8]), ah);
        ldsm_x4(smem_u32(&sWl[(ogrp * 16 + lr) * 72 + kk * 16 + lh * 8]), al);
#pragma unroll
        for (int j = 0; j < 4; j++) {
            int rowk = (kk << 4) + ((bq & 1) << 3) + br;
            int colm = (mgrp << 6) + (j << 4) + ((bq >> 1) << 3);
            uint32_t bh[4], bl[4];
            ldsm_x4t(smem_u32(&sGh[rowk * 136 + colm]), bh);
            mma_bf16(acc[j * 2], ah, bh[0], bh[1]);
            mma_bf16(acc[j * 2 + 1], ah, bh[2], bh[3]);
            mma_bf16(acc[j * 2], al, bh[0], bh[1]);
            mma_bf16(acc[j * 2 + 1], al, bh[2], bh[3]);
            ldsm_x4t(smem_u32(&sGl[rowk * 136 + colm]), bl);
            mma_bf16(acc[j * 2], ah, bl[0], bl[1]);
            mma_bf16(acc[j * 2 + 1], ah, bl[2], bl[3]);
        }
    }
    int o = (ogrp << 4) + (lane >> 2);
    size_t rowa = ((size_t)(b << 6) + o) * Nn + m0;
    size_t rowb2 = ((size_t)(b << 6) + o + 8) * Nn + m0;
#pragma unroll
    for (int f = 0; f < 8; f++) {
        int mm = (mgrp << 6) + ((f >> 1) << 4) + ((f & 1) << 3) + ((lane & 3) << 1);
        float i0 = szm[mm], i1 = szm[mm + 1];
        uint32_t h, l;
        split2(acc[f].x * i0, acc[f].y * i1, h, l);
        *(uint32_t*)&g_gzH[rowa + mm] = h;
        *(uint32_t*)&g_gzL[rowa + mm] = l;
        split2(acc[f].z * i0, acc[f].w * i1, h, l);
        *(uint32_t*)&g_gzH[rowb2 + mm] = h;
        *(uint32_t*)&g_gzL[rowb2 + mm] = l;
    }
}

// ---------------- K4: out[o][n] = sum_m gz[o][m] E[m][n] + x (cp.async pipe)
__global__ __launch_bounds__(256, 2) void k4_out_mma(
    const float* __restrict__ x, float* __restrict__ out) {
    extern __shared__ __align__(16) char sm4[];
    uint32_t sb = smem_u32(sm4);
    int b = blockIdx.x, n0 = blockIdx.y << 7;
    int t = threadIdx.x, w = t >> 5, lane = t & 31;
    int ogrp = w & 3, ngrp = w >> 2;

    float4 acc[8] = {};
    int lr = lane & 15, lh = lane >> 4;
    int bq = lane >> 3, br = lane & 7;

    auto stage = [&](int mc, int buf) {
        uint32_t base = sb + buf * 53248u;
        uint32_t aH = base, aL = base + 9216u, bH = base + 18432u, bL = base + 35840u;
#pragma unroll
        for (int i = 0; i < 2; i++) {
            int lin = t + (i << 8);
            int r = lin >> 3, q = lin & 7;
            size_t gofs = ((size_t)(b << 6) + r) * Nn + mc + (q << 3);
            cpa16(aH + r * 144 + (q << 4), &g_gzH[gofs]);
            cpa16(aL + r * 144 + (q << 4), &g_gzL[gofs]);
        }
#pragma unroll
        for (int i = 0; i < 4; i++) {
            int lin = t + (i << 8);
            int r = lin >> 4, q = lin & 15;
            size_t off = ((size_t)(b * Nn) + mc + r) * Nn + n0 + (q << 3);
            cpa16(bH + r * 272 + (q << 4), &g_EH[off]);
            cpa16(bL + r * 272 + (q << 4), &g_EL[off]);
        }
        CPA_COMMIT();
    };

    stage(0, 0);
    for (int ci = 0; ci < 16; ci++) {
        int buf = ci & 1;
        if (ci + 1 < 16) { stage((ci + 1) << 6, buf ^ 1); CPA_WAIT(1); }
        else { CPA_WAIT(0); }
        __syncthreads();
        uint32_t base = sb + buf * 53248u;
        uint32_t aH = base, aL = base + 9216u, bH = base + 18432u, bL = base + 35840u;
#pragma unroll
        for (int kk = 0; kk < 4; kk++) {
            uint32_t ah[4], al[4];
            uint32_t arow = (ogrp * 16 + lr) * 144 + kk * 32 + lh * 16;
            ldsm_x4(aH + arow, ah);
            ldsm_x4(aL + arow, al);
#pragma unroll
            for (int j = 0; j < 4; j++) {
                int rowm = (kk << 4) + ((bq & 1) << 3) + br;
                int coln = (ngrp << 6) + (j << 4) + ((bq >> 1) << 3);
                uint32_t boff = rowm * 272 + coln * 2;
                uint32_t bh[4], bl[4];
                ldsm_x4t(bH + boff, bh);
                mma_bf16(acc[j * 2], ah, bh[0], bh[1]);
                mma_bf16(acc[j * 2 + 1], ah, bh[2], bh[3]);
                mma_bf16(acc[j * 2], al, bh[0], bh[1]);
                mma_bf16(acc[j * 2 + 1], al, bh[2], bh[3]);
                ldsm_x4t(bL + boff, bl);
                mma_bf16(acc[j * 2], ah, bl[0], bl[1]);
                mma_bf16(acc[j * 2 + 1], ah, bl[2], bl[3]);
            }
        }
        __syncthreads();
    }
    int o = (ogrp << 4) + (lane >> 2);
#pragma unroll
    for (int f = 0; f < 8; f++) {
        int n = n0 + (ngrp << 6) + ((f >> 1) << 4) + ((f & 1) << 3) + ((lane & 3) << 1);
        size_t off = ((size_t)(b << 6) + o) * Nn + n;
        float2 xv = *(const float2*)&x[off];
        *(float2*)&out[off] = make_float2(acc[f].x + xv.x, acc[f].y + xv.y);
        size_t off2 = off + (size_t)8 * Nn;
        float2 xv2 = *(const float2*)&x[off2];
        *(float2*)&out[off2] = make_float2(acc[f].z + xv2.x, acc[f].w + xv2.y);
    }
}

// ---------------- launch ----------------------------------------------------
extern "C" void kernel_launch(void* const* d_in, const int* in_sizes, int n_in,
                              void* d_out, int out_size) {
    const float* x      = (const float*)d_in[0];
    const float* wphi   = (const float*)d_in[1];
    const float* wtheta = (const float*)d_in[2];
    const float* wg     = (const float*)d_in[3];
    const float* wmask  = (const float*)d_in[4];
    const float* wmv    = (const float*)d_in[5];
    const float* wmk    = (const float*)d_in[6];
    float* out = (float*)d_out;

    cudaFuncSetAttribute(k1_mma, cudaFuncAttributeMaxDynamicSharedMemorySize, 90112);
    cudaFuncSetAttribute(k2_P_mma, cudaFuncAttributeMaxDynamicSharedMemorySize, 110592);
    cudaFuncSetAttribute(k3_att_mma, cudaFuncAttributeMaxDynamicSharedMemorySize, 69632);
    cudaFuncSetAttribute(k5_gmz_mma, cudaFuncAttributeMaxDynamicSharedMemorySize, 53760);
    cudaFuncSetAttribute(k4_out_mma, cudaFuncAttributeMaxDynamicSharedMemorySize, 106496);

    k0_prep<<<128, 256>>>(wmv, wg, wphi, wtheta, wmask);
    k0w_split<<<1024, 256>>>(wmk);
    k1_mma<<<dim3(32, 8), 256, 90112>>>(x);
    k2_P_mma<<<dim3(32, 8), 256, 110592>>>();
    k3_att_mma<<<dim3(8, 8, 32), 256, 69632>>>();
    k5_gmz_mma<<<dim3(32, 8), 256, 53760>>>();
    k4_out_mma<<<dim3(32, 8), 256, 106496>>>(x, out);
}

// round 10
// speedup vs baseline: 2.0356x; 1.0114x over previous
#include <cuda_runtime.h>
#include <cuda_bf16.h>
#include <cstdint>

#define Bq 32
#define Cc 64
#define Nn 1024

// ---------------- scratch (device globals) ----------------------------------
__device__ __nv_bfloat16 g_phiH[Bq * Cc * Nn];  // [b][c][m]
__device__ __nv_bfloat16 g_phiL[Bq * Cc * Nn];
__device__ __nv_bfloat16 g_wmkH[Nn * Nn];       // [k][m]
__device__ __nv_bfloat16 g_wmkL[Nn * Nn];
__device__ __nv_bfloat16 g_thH[Bq * Cc * Nn];   // [b][c][n] theta hi/lo
__device__ __nv_bfloat16 g_thL[Bq * Cc * Nn];
__device__ __nv_bfloat16 g_PH[Bq * Cc * Nn];    // [b][c][k] P hi/lo
__device__ __nv_bfloat16 g_PL[Bq * Cc * Nn];
__device__ float g_gm[Bq * Cc * Nn];            // [b][c][n]
__device__ __nv_bfloat16 g_EH[(size_t)Bq * Nn * Nn];  // [b][k][n] exp hi (64MB)
__device__ __nv_bfloat16 g_EL[(size_t)Bq * Nn * Nn];  // [b][k][n] exp lo (64MB)
__device__ float g_Z[Bq * Nn];
__device__ __nv_bfloat16 g_gzH[Bq * Cc * Nn];   // [b][o][m] (w_mask@gm)/Z hi/lo
__device__ __nv_bfloat16 g_gzL[Bq * Cc * Nn];
// small weight splits (filled by k0)
__device__ __nv_bfloat16 g_wphiH[Cc * Cc], g_wphiL[Cc * Cc];
__device__ __nv_bfloat16 g_wthH[Cc * Cc],  g_wthL[Cc * Cc];
__device__ __nv_bfloat16 g_wgvH[Cc * Cc],  g_wgvL[Cc * Cc];
__device__ __nv_bfloat16 g_wmaskH[Cc * Cc], g_wmaskL[Cc * Cc];

// ---------------- mma.sync / cp.async helpers -------------------------------
__device__ __forceinline__ uint32_t smem_u32(const void* p) {
    uint32_t a;
    asm("{ .reg .u64 t; cvta.to.shared.u64 t, %1; cvt.u32.u64 %0, t; }"
        : "=r"(a) : "l"(p));
    return a;
}
__device__ __forceinline__ void ldsm_x4(uint32_t addr, uint32_t r[4]) {
    asm volatile("ldmatrix.sync.aligned.m8n8.x4.shared.b16 {%0,%1,%2,%3}, [%4];"
                 : "=r"(r[0]), "=r"(r[1]), "=r"(r[2]), "=r"(r[3]) : "r"(addr));
}
__device__ __forceinline__ void ldsm_x4t(uint32_t addr, uint32_t r[4]) {
    asm volatile("ldmatrix.sync.aligned.m8n8.x4.trans.shared.b16 {%0,%1,%2,%3}, [%4];"
                 : "=r"(r[0]), "=r"(r[1]), "=r"(r[2]), "=r"(r[3]) : "r"(addr));
}
__device__ __forceinline__ void mma_bf16(float4& d, const uint32_t a[4],
                                         uint32_t b0, uint32_t b1) {
    asm volatile(
        "mma.sync.aligned.m16n8k16.row.col.f32.bf16.bf16.f32 "
        "{%0,%1,%2,%3}, {%4,%5,%6,%7}, {%8,%9}, {%0,%1,%2,%3};"
        : "+f"(d.x), "+f"(d.y), "+f"(d.z), "+f"(d.w)
        : "r"(a[0]), "r"(a[1]), "r"(a[2]), "r"(a[3]), "r"(b0), "r"(b1));
}
__device__ __forceinline__ void cpa16(uint32_t s, const void* g) {
    asm volatile("cp.async.cg.shared.global [%0], [%1], 16;" :: "r"(s), "l"(g));
}
#define CPA_COMMIT() asm volatile("cp.async.commit_group;" ::: "memory")
#define CPA_WAIT(n) asm volatile("cp.async.wait_group %0;" :: "n"(n) : "memory")

__device__ __forceinline__ uint32_t bfpack(float a, float b) {
    __nv_bfloat162 h;
    h.x = __float2bfloat16(a); h.y = __float2bfloat16(b);
    return *(uint32_t*)&h;
}
__device__ __forceinline__ void split4(float4 v, uint2& hi, uint2& lo) {
    uint32_t hA = bfpack(v.x, v.y), hB = bfpack(v.z, v.w);
    __nv_bfloat162* hp = (__nv_bfloat162*)&hA;
    __nv_bfloat162* hq = (__nv_bfloat162*)&hB;
    uint32_t lA = bfpack(v.x - __bfloat162float(hp->x), v.y - __bfloat162float(hp->y));
    uint32_t lB = bfpack(v.z - __bfloat162float(hq->x), v.w - __bfloat162float(hq->y));
    hi = make_uint2(hA, hB); lo = make_uint2(lA, lB);
}
__device__ __forceinline__ void split2(float a, float b, uint32_t& h, uint32_t& l) {
    h = bfpack(a, b);
    __nv_bfloat162* hp = (__nv_bfloat162*)&h;
    l = bfpack(a - __bfloat162float(hp->x), b - __bfloat162float(hp->y));
}

// ---------------- K0: zero Z, wgv = w_mv @ w_g, split small weights ---------
__global__ void k0_prep(const float* __restrict__ wmv, const float* __restrict__ wg,
                        const float* __restrict__ wphi, const float* __restrict__ wtheta,
                        const float* __restrict__ wmask) {
    int t = blockIdx.x * blockDim.x + threadIdx.x;
    if (t < Bq * Nn) g_Z[t] = 0.0f;
    if (t < Cc * Cc) {
        int d = t >> 6, ci = t & 63;
        float s = 0.0f;
#pragma unroll
        for (int c = 0; c < 64; c++) s += wmv[d * 64 + c] * wg[c * 64 + ci];
        __nv_bfloat16 h;
        h = __float2bfloat16(s);
        g_wgvH[t] = h; g_wgvL[t] = __float2bfloat16(s - __bfloat162float(h));
        float v = wphi[t];
        h = __float2bfloat16(v);
        g_wphiH[t] = h; g_wphiL[t] = __float2bfloat16(v - __bfloat162float(h));
        v = wtheta[t];
        h = __float2bfloat16(v);
        g_wthH[t] = h; g_wthL[t] = __float2bfloat16(v - __bfloat162float(h));
        v = wmask[t];
        h = __float2bfloat16(v);
        g_wmaskH[t] = h; g_wmaskL[t] = __float2bfloat16(v - __bfloat162float(h));
    }
}

// ---------------- K0w: split wmk into bf16 hi/lo ----------------------------
__global__ __launch_bounds__(256) void k0w_split(const float* __restrict__ wmk) {
    int i = blockIdx.x * 256 + threadIdx.x;
    float4 v = ((const float4*)wmk)[i];
    uint2 hi, lo;
    split4(v, hi, lo);
    ((uint2*)g_wmkH)[i] = hi;
    ((uint2*)g_wmkL)[i] = lo;
}

// ---------------- K1: channel GEMMs via mma.sync (phi, theta, gm) -----------
__global__ __launch_bounds__(256, 2) void k1_mma(const float* __restrict__ x) {
    extern __shared__ __align__(16) char sm1[];
    __nv_bfloat16* sXh = (__nv_bfloat16*)sm1;
    __nv_bfloat16* sXl = (__nv_bfloat16*)(sm1 + 17408);
    __nv_bfloat16* sW[6] = {
        (__nv_bfloat16*)(sm1 + 34816), (__nv_bfloat16*)(sm1 + 44032),
        (__nv_bfloat16*)(sm1 + 53248), (__nv_bfloat16*)(sm1 + 62464),
        (__nv_bfloat16*)(sm1 + 71680), (__nv_bfloat16*)(sm1 + 80896)};
    int b = blockIdx.x, n0 = blockIdx.y << 7;
    int t = threadIdx.x, w = t >> 5, lane = t & 31;
    int cgrp = w & 3, ngrp = w >> 2;

#pragma unroll
    for (int i = 0; i < 8; i++) {
        int lin = t + (i << 8);
        int r = lin >> 5, q = lin & 31;
        float4 v = *(const float4*)&x[((size_t)(b << 6) + r) * Nn + n0 + (q << 2)];
        uint2 hi, lo;
        split4(v, hi, lo);
        *(uint2*)&sXh[r * 136 + (q << 2)] = hi;
        *(uint2*)&sXl[r * 136 + (q << 2)] = lo;
    }
    {
        const __nv_bfloat16* src[6] = {g_wphiH, g_wphiL, g_wthH, g_wthL, g_wgvH, g_wgvL};
#pragma unroll
        for (int a = 0; a < 6; a++)
#pragma unroll
            for (int i = 0; i < 2; i++) {
                int lin = t + (i << 8);
                int r = lin >> 3, q = lin & 7;
                *(uint4*)&sW[a][r * 72 + (q << 3)] = *(const uint4*)&src[a][r * 64 + (q << 3)];
            }
    }
    __syncthreads();

    int lr = lane & 15, lh = lane >> 4;
    int bq = lane >> 3, br = lane & 7;

#pragma unroll
    for (int p = 0; p < 3; p++) {
        float4 acc[8] = {};
        __nv_bfloat16* WH = sW[p * 2];
        __nv_bfloat16* WL = sW[p * 2 + 1];
#pragma unroll
        for (int kk = 0; kk < 4; kk++) {
            uint32_t ah[4], al[4];
            ldsm_x4(smem_u32(&WH[(cgrp * 16 + lr) * 72 + kk * 16 + lh * 8]), ah);
            ldsm_x4(smem_u32(&WL[(cgrp * 16 + lr) * 72 + kk * 16 + lh * 8]), al);
#pragma unroll
            for (int j = 0; j < 4; j++) {
                int rowk = (kk << 4) + ((bq & 1) << 3) + br;
                int coln = (ngrp << 6) + (j << 4) + ((bq >> 1) << 3);
                uint32_t bh[4], bl[4];
                ldsm_x4t(smem_u32(&sXh[rowk * 136 + coln]), bh);
                mma_bf16(acc[j * 2], ah, bh[0], bh[1]);
                mma_bf16(acc[j * 2 + 1], ah, bh[2], bh[3]);
                mma_bf16(acc[j * 2], al, bh[0], bh[1]);
                mma_bf16(acc[j * 2 + 1], al, bh[2], bh[3]);
                ldsm_x4t(smem_u32(&sXl[rowk * 136 + coln]), bl);
                mma_bf16(acc[j * 2], ah, bl[0], bl[1]);
                mma_bf16(acc[j * 2 + 1], ah, bl[2], bl[3]);
            }
        }
        int m = (cgrp << 4) + (lane >> 2);
        if (p == 2) {
            float* O = g_gm + (size_t)(b << 6) * Nn;
#pragma unroll
            for (int f = 0; f < 8; f++) {
                int n = n0 + (ngrp << 6) + ((f >> 1) << 4) + ((f & 1) << 3) + ((lane & 3) << 1);
                *(float2*)&O[(size_t)m * Nn + n] = make_float2(acc[f].x, acc[f].y);
                *(float2*)&O[(size_t)(m + 8) * Nn + n] = make_float2(acc[f].z, acc[f].w);
            }
        } else {
            __nv_bfloat16* H = (p == 0 ? g_phiH : g_thH);
            __nv_bfloat16* L = (p == 0 ? g_phiL : g_thL);
            size_t rowa = ((size_t)(b << 6) + m) * Nn;
            size_t rowb2 = ((size_t)(b << 6) + m + 8) * Nn;
#pragma unroll
            for (int f = 0; f < 8; f++) {
                int n = n0 + (ngrp << 6) + ((f >> 1) << 4) + ((f & 1) << 3) + ((lane & 3) << 1);
                uint32_t h, l;
                split2(acc[f].x, acc[f].y, h, l);
                *(uint32_t*)&H[rowa + n] = h;
                *(uint32_t*)&L[rowa + n] = l;
                split2(acc[f].z, acc[f].w, h, l);
                *(uint32_t*)&H[rowb2 + n] = h;
                *(uint32_t*)&L[rowb2 + n] = l;
            }
        }
    }
}

// ---------------- K2: P = phi @ wmk^T (mma.sync bf16x3, cp.async, 4 warps) --
// grid (32 b, 8 ktile), block 128 = 4 warps. Warp tile 16c x 128k. Chunk 64.
__global__ __launch_bounds__(128, 2) void k2_P_mma(void) {
    extern __shared__ __align__(16) char sm2[];
    uint32_t sb = smem_u32(sm2);
    int b = blockIdx.x, k0 = blockIdx.y << 7;
    int t = threadIdx.x, w = t >> 5, lane = t & 31;

    const __nv_bfloat16* Ah = g_phiH + (size_t)(b << 6) * Nn;
    const __nv_bfloat16* Al = g_phiL + (size_t)(b << 6) * Nn;

    float4 acc[16] = {};
    int lr = lane & 15, lh = lane >> 4;
    int bq = lane >> 3, br = lane & 7;

    auto stage = [&](int mc, int buf) {
        uint32_t base = sb + buf * 55296u;
        uint32_t aH = base, aL = base + 9216u, bH = base + 18432u, bL = base + 36864u;
#pragma unroll
        for (int i = 0; i < 4; i++) {
            int lin = t + (i << 7);
            int r = lin >> 3, q = lin & 7;
            cpa16(aH + r * 144 + (q << 4), &Ah[(size_t)r * Nn + mc + (q << 3)]);
            cpa16(aL + r * 144 + (q << 4), &Al[(size_t)r * Nn + mc + (q << 3)]);
        }
#pragma unroll
        for (int i = 0; i < 8; i++) {
            int lin = t + (i << 7);
            int r = lin >> 3, q = lin & 7;
            cpa16(bH + r * 144 + (q << 4), &g_wmkH[(size_t)(k0 + r) * Nn + mc + (q << 3)]);
            cpa16(bL + r * 144 + (q << 4), &g_wmkL[(size_t)(k0 + r) * Nn + mc + (q << 3)]);
        }
        CPA_COMMIT();
    };

    stage(0, 0);
    for (int ci = 0; ci < 16; ci++) {
        int buf = ci & 1;
        if (ci + 1 < 16) { stage((ci + 1) << 6, buf ^ 1); CPA_WAIT(1); }
        else { CPA_WAIT(0); }
        __syncthreads();
        uint32_t base = sb + buf * 55296u;
        uint32_t aH = base, aL = base + 9216u, bH = base + 18432u, bL = base + 36864u;
#pragma unroll
        for (int kk = 0; kk < 4; kk++) {
            uint32_t ah[4], al[4];
            uint32_t arow = (w * 16 + lr) * 144 + kk * 32 + lh * 16;
            ldsm_x4(aH + arow, ah);
            ldsm_x4(aL + arow, al);
#pragma unroll
            for (int j = 0; j < 8; j++) {
                int rowb = (j << 4) + ((bq >> 1) << 3) + br;
                uint32_t boff = rowb * 144 + kk * 32 + ((bq & 1) << 4);
                uint32_t bh[4], bl[4];
                ldsm_x4(bH + boff, bh);
                mma_bf16(acc[j * 2], ah, bh[0], bh[1]);
                mma_bf16(acc[j * 2 + 1], ah, bh[2], bh[3]);
                mma_bf16(acc[j * 2], al, bh[0], bh[1]);
                mma_bf16(acc[j * 2 + 1], al, bh[2], bh[3]);
                ldsm_x4(bL + boff, bl);
                mma_bf16(acc[j * 2], ah, bl[0], bl[1]);
                mma_bf16(acc[j * 2 + 1], ah, bl[2], bl[3]);
            }
        }
        __syncthreads();
    }

    int m = (w << 4) + (lane >> 2);
    size_t prow = ((size_t)(b << 6) + m) * Nn + k0;
#pragma unroll
    for (int f = 0; f < 16; f++) {
        int n = ((f >> 1) << 4) + ((f & 1) << 3) + ((lane & 3) << 1);
        uint32_t h, l;
        split2(acc[f].x, acc[f].y, h, l);
        *(uint32_t*)&g_PH[prow + n] = h;
        *(uint32_t*)&g_PL[prow + n] = l;
        split2(acc[f].z, acc[f].w, h, l);
        *(uint32_t*)&g_PH[prow + 8 * Nn + n] = h;
        *(uint32_t*)&g_PL[prow + 8 * Nn + n] = l;
    }
}

// ---------------- K3: Et = exp(P^T theta), bf16 hi/lo out, Z sums -----------
__global__ __launch_bounds__(256, 2) void k3_att_mma(void) {
    extern __shared__ __align__(16) char sm3[];
    __nv_bfloat16* sPh = (__nv_bfloat16*)sm3;              // [64][136]
    __nv_bfloat16* sPl = (__nv_bfloat16*)(sm3 + 17408);
    __nv_bfloat16* sTh = (__nv_bfloat16*)(sm3 + 34816);
    __nv_bfloat16* sTl = (__nv_bfloat16*)(sm3 + 52224);
    int b = blockIdx.z, k0 = blockIdx.x << 7, n0 = blockIdx.y << 7;
    int t = threadIdx.x, w = t >> 5, lane = t & 31;
    int kw = w & 3, nw = w >> 2;

#pragma unroll
    for (int i = 0; i < 4; i++) {
        int lin = t + (i << 8);
        int r = lin >> 4, q = lin & 15;
        size_t pofs = ((size_t)(b << 6) + r) * Nn + k0 + (q << 3);
        size_t tofs = ((size_t)(b << 6) + r) * Nn + n0 + (q << 3);
        *(uint4*)&sPh[r * 136 + (q << 3)] = *(const uint4*)&g_PH[pofs];
        *(uint4*)&sPl[r * 136 + (q << 3)] = *(const uint4*)&g_PL[pofs];
        *(uint4*)&sTh[r * 136 + (q << 3)] = *(const uint4*)&g_thH[tofs];
        *(uint4*)&sTl[r * 136 + (q << 3)] = *(const uint4*)&g_thL[tofs];
    }
    __syncthreads();

    float4 acc[2][8] = {};
    int bq = lane >> 3, br = lane & 7;
#pragma unroll
    for (int kk = 0; kk < 4; kk++) {
        int c0 = kk << 4;
        uint32_t ah[2][4], al[2][4];
#pragma unroll
        for (int mt = 0; mt < 2; mt++) {
            int m0 = (kw << 5) + (mt << 4);
            int rowc = c0 + ((bq >> 1) << 3) + br;
            int colm = m0 + ((bq & 1) << 3);
            ldsm_x4t(smem_u32(&sPh[rowc * 136 + colm]), ah[mt]);
            ldsm_x4t(smem_u32(&sPl[rowc * 136 + colm]), al[mt]);
        }
#pragma unroll
        for (int j = 0; j < 4; j++) {
            int rowc = c0 + ((bq & 1) << 3) + br;
            int coln = (nw << 6) + (j << 4) + ((bq >> 1) << 3);
            uint32_t bh[4], bl[4];
            ldsm_x4t(smem_u32(&sTh[rowc * 136 + coln]), bh);
            ldsm_x4t(smem_u32(&sTl[rowc * 136 + coln]), bl);
#pragma unroll
            for (int mt = 0; mt < 2; mt++) {
                mma_bf16(acc[mt][j * 2], ah[mt], bh[0], bh[1]);
                mma_bf16(acc[mt][j * 2 + 1], ah[mt], bh[2], bh[3]);
                mma_bf16(acc[mt][j * 2], al[mt], bh[0], bh[1]);
                mma_bf16(acc[mt][j * 2 + 1], al[mt], bh[2], bh[3]);
                mma_bf16(acc[mt][j * 2], ah[mt], bl[0], bl[1]);
                mma_bf16(acc[mt][j * 2 + 1], ah[mt], bl[2], bl[3]);
            }
        }
    }

    __syncthreads();
    __nv_bfloat16* sEH = (__nv_bfloat16*)sm3;
    __nv_bfloat16* sEL = (__nv_bfloat16*)(sm3 + 34816);
#pragma unroll
    for (int mt = 0; mt < 2; mt++) {
        int krow = (kw << 5) + (mt << 4) + (lane >> 2);
        float sA = 0.f, sB = 0.f;
#pragma unroll
        for (int j = 0; j < 8; j++) {
            int nc = (nw << 6) + (j << 3) + ((lane & 3) << 1);
            float ex = __expf(acc[mt][j].x), ey = __expf(acc[mt][j].y);
            float ez = __expf(acc[mt][j].z), ew = __expf(acc[mt][j].w);
            sA += ex + ey; sB += ez + ew;
            uint32_t h0, l0, h1, l1;
            split2(ex, ey, h0, l0);
            split2(ez, ew, h1, l1);
            *(uint32_t*)&sEH[krow * 136 + nc] = h0;
            *(uint32_t*)&sEL[krow * 136 + nc] = l0;
            *(uint32_t*)&sEH[(krow + 8) * 136 + nc] = h1;
            *(uint32_t*)&sEL[(krow + 8) * 136 + nc] = l1;
        }
        sA += __shfl_xor_sync(0xffffffffu, sA, 1);
        sA += __shfl_xor_sync(0xffffffffu, sA, 2);
        sB += __shfl_xor_sync(0xffffffffu, sB, 1);
        sB += __shfl_xor_sync(0xffffffffu, sB, 2);
        if ((lane & 3) == 0) {
            atomicAdd(&g_Z[b * Nn + k0 + krow], sA);
            atomicAdd(&g_Z[b * Nn + k0 + krow + 8], sB);
        }
    }
    __syncthreads();
#pragma unroll
    for (int i = 0; i < 8; i++) {
        int lin = t + (i << 8);
        int r = lin >> 4, q = lin & 15;
        size_t off = ((size_t)(b * Nn + k0 + r)) * Nn + n0 + (q << 3);
        *(uint4*)&g_EH[off] = *(uint4*)&sEH[r * 136 + (q << 3)];
        *(uint4*)&g_EL[off] = *(uint4*)&sEL[r * 136 + (q << 3)];
    }
}

// ---------------- K5: gz = (wmask@gm)/Z via mma.sync, bf16 hi/lo out --------
__global__ __launch_bounds__(256, 2) void k5_gmz_mma(void) {
    extern __shared__ __align__(16) char sm5[];
    __nv_bfloat16* sGh = (__nv_bfloat16*)sm5;
    __nv_bfloat16* sGl = (__nv_bfloat16*)(sm5 + 17408);
    __nv_bfloat16* sWh = (__nv_bfloat16*)(sm5 + 34816);
    __nv_bfloat16* sWl = (__nv_bfloat16*)(sm5 + 44032);
    float* szm = (float*)(sm5 + 53248);
    int b = blockIdx.x, m0 = blockIdx.y << 7;
    int t = threadIdx.x, w = t >> 5, lane = t & 31;
    int ogrp = w & 3, mgrp = w >> 2;

    const float* gm = g_gm + (size_t)(b << 6) * Nn;
#pragma unroll
    for (int i = 0; i < 8; i++) {
        int lin = t + (i << 8);
        int r = lin >> 5, q = lin & 31;
        float4 v = *(const float4*)&gm[(size_t)r * Nn + m0 + (q << 2)];
        uint2 hi, lo;
        split4(v, hi, lo);
        *(uint2*)&sGh[r * 136 + (q << 2)] = hi;
        *(uint2*)&sGl[r * 136 + (q << 2)] = lo;
    }
#pragma unroll
    for (int i = 0; i < 2; i++) {
        int lin = t + (i << 8);
        int r = lin >> 3, q = lin & 7;
        *(uint4*)&sWh[r * 72 + (q << 3)] = *(const uint4*)&g_wmaskH[r * 64 + (q << 3)];
        *(uint4*)&sWl[r * 72 + (q << 3)] = *(const uint4*)&g_wmaskL[r * 64 + (q << 3)];
    }
    if (t < 128) szm[t] = 1.0f / g_Z[b * Nn + m0 + t];
    __syncthreads();

    int lr = lane & 15, lh = lane >> 4;
    int bq = lane >> 3, br = lane & 7;

    float4 acc[8] = {};
#pragma unroll
    for (int kk = 0; kk < 4; kk++) {
        uint32_t ah[4], al[4];
        ldsm_x4(smem_u32(&sWh[(ogrp * 16 + lr) * 72 + kk * 16 + lh * 8]), ah);
        ldsm_x4(smem_u32(&sWl[(ogrp * 16 + lr) * 72 + kk * 16 + lh * 8]), al);
#pragma unroll
        for (int j = 0; j < 4; j++) {
            int rowk = (kk << 4) + ((bq & 1) << 3) + br;
            int colm = (mgrp << 6) + (j << 4) + ((bq >> 1) << 3);
            uint32_t bh[4], bl[4];
            ldsm_x4t(smem_u32(&sGh[rowk * 136 + colm]), bh);
            mma_bf16(acc[j * 2], ah, bh[0], bh[1]);
            mma_bf16(acc[j * 2 + 1], ah, bh[2], bh[3]);
            mma_bf16(acc[j * 2], al, bh[0], bh[1]);
            mma_bf16(acc[j * 2 + 1], al, bh[2], bh[3]);
            ldsm_x4t(smem_u32(&sGl[rowk * 136 + colm]), bl);
            mma_bf16(acc[j * 2], ah, bl[0], bl[1]);
            mma_bf16(acc[j * 2 + 1], ah, bl[2], bl[3]);
        }
    }
    int o = (ogrp << 4) + (lane >> 2);
    size_t rowa = ((size_t)(b << 6) + o) * Nn + m0;
    size_t rowb2 = ((size_t)(b << 6) + o + 8) * Nn + m0;
#pragma unroll
    for (int f = 0; f < 8; f++) {
        int mm = (mgrp << 6) + ((f >> 1) << 4) + ((f & 1) << 3) + ((lane & 3) << 1);
        float i0 = szm[mm], i1 = szm[mm + 1];
        uint32_t h, l;
        split2(acc[f].x * i0, acc[f].y * i1, h, l);
        *(uint32_t*)&g_gzH[rowa + mm] = h;
        *(uint32_t*)&g_gzL[rowa + mm] = l;
        split2(acc[f].z * i0, acc[f].w * i1, h, l);
        *(uint32_t*)&g_gzH[rowb2 + mm] = h;
        *(uint32_t*)&g_gzL[rowb2 + mm] = l;
    }
}

// ---------------- K4: out = gz @ E + x (cp.async pipe, 4 warps) -------------
// grid (32 b, 8 ntile), block 128 = 4 warps. Warp tile 16o x 128n. Chunk 64.
__global__ __launch_bounds__(128, 2) void k4_out_mma(
    const float* __restrict__ x, float* __restrict__ out) {
    extern __shared__ __align__(16) char sm4[];
    uint32_t sb = smem_u32(sm4);
    int b = blockIdx.x, n0 = blockIdx.y << 7;
    int t = threadIdx.x, w = t >> 5, lane = t & 31;

    float4 acc[16] = {};
    int lr = lane & 15, lh = lane >> 4;
    int bq = lane >> 3, br = lane & 7;

    auto stage = [&](int mc, int buf) {
        uint32_t base = sb + buf * 53248u;
        uint32_t aH = base, aL = base + 9216u, bH = base + 18432u, bL = base + 35840u;
#pragma unroll
        for (int i = 0; i < 4; i++) {
            int lin = t + (i << 7);
            int r = lin >> 3, q = lin & 7;
            size_t gofs = ((size_t)(b << 6) + r) * Nn + mc + (q << 3);
            cpa16(aH + r * 144 + (q << 4), &g_gzH[gofs]);
            cpa16(aL + r * 144 + (q << 4), &g_gzL[gofs]);
        }
#pragma unroll
        for (int i = 0; i < 8; i++) {
            int lin = t + (i << 7);
            int r = lin >> 4, q = lin & 15;
            size_t off = ((size_t)(b * Nn) + mc + r) * Nn + n0 + (q << 3);
            cpa16(bH + r * 272 + (q << 4), &g_EH[off]);
            cpa16(bL + r * 272 + (q << 4), &g_EL[off]);
        }
        CPA_COMMIT();
    };

    stage(0, 0);
    for (int ci = 0; ci < 16; ci++) {
        int buf = ci & 1;
        if (ci + 1 < 16) { stage((ci + 1) << 6, buf ^ 1); CPA_WAIT(1); }
        else { CPA_WAIT(0); }
        __syncthreads();
        uint32_t base = sb + buf * 53248u;
        uint32_t aH = base, aL = base + 9216u, bH = base + 18432u, bL = base + 35840u;
#pragma unroll
        for (int kk = 0; kk < 4; kk++) {
            uint32_t ah[4], al[4];
            uint32_t arow = (w * 16 + lr) * 144 + kk * 32 + lh * 16;
            ldsm_x4(aH + arow, ah);
            ldsm_x4(aL + arow, al);
#pragma unroll
            for (int j = 0; j < 8; j++) {
                int rowm = (kk << 4) + ((bq & 1) << 3) + br;
                int coln = (j << 4) + ((bq >> 1) << 3);
                uint32_t boff = rowm * 272 + coln * 2;
                uint32_t bh[4], bl[4];
                ldsm_x4t(bH + boff, bh);
                mma_bf16(acc[j * 2], ah, bh[0], bh[1]);
                mma_bf16(acc[j * 2 + 1], ah, bh[2], bh[3]);
                mma_bf16(acc[j * 2], al, bh[0], bh[1]);
                mma_bf16(acc[j * 2 + 1], al, bh[2], bh[3]);
                ldsm_x4t(bL + boff, bl);
                mma_bf16(acc[j * 2], ah, bl[0], bl[1]);
                mma_bf16(acc[j * 2 + 1], ah, bl[2], bl[3]);
            }
        }
        __syncthreads();
    }
    int o = (w << 4) + (lane >> 2);
#pragma unroll
    for (int f = 0; f < 16; f++) {
        int n = n0 + ((f >> 1) << 4) + ((f & 1) << 3) + ((lane & 3) << 1);
        size_t off = ((size_t)(b << 6) + o) * Nn + n;
        float2 xv = *(const float2*)&x[off];
        *(float2*)&out[off] = make_float2(acc[f].x + xv.x, acc[f].y + xv.y);
        size_t off2 = off + (size_t)8 * Nn;
        float2 xv2 = *(const float2*)&x[off2];
        *(float2*)&out[off2] = make_float2(acc[f].z + xv2.x, acc[f].w + xv2.y);
    }
}

// ---------------- launch ----------------------------------------------------
extern "C" void kernel_launch(void* const* d_in, const int* in_sizes, int n_in,
                              void* d_out, int out_size) {
    const float* x      = (const float*)d_in[0];
    const float* wphi   = (const float*)d_in[1];
    const float* wtheta = (const float*)d_in[2];
    const float* wg     = (const float*)d_in[3];
    const float* wmask  = (const float*)d_in[4];
    const float* wmv    = (const float*)d_in[5];
    const float* wmk    = (const float*)d_in[6];
    float* out = (float*)d_out;

    cudaFuncSetAttribute(k1_mma, cudaFuncAttributeMaxDynamicSharedMemorySize, 90112);
    cudaFuncSetAttribute(k2_P_mma, cudaFuncAttributeMaxDynamicSharedMemorySize, 110592);
    cudaFuncSetAttribute(k3_att_mma, cudaFuncAttributeMaxDynamicSharedMemorySize, 69632);
    cudaFuncSetAttribute(k5_gmz_mma, cudaFuncAttributeMaxDynamicSharedMemorySize, 53760);
    cudaFuncSetAttribute(k4_out_mma, cudaFuncAttributeMaxDynamicSharedMemorySize, 106496);

    k0_prep<<<128, 256>>>(wmv, wg, wphi, wtheta, wmask);
    k0w_split<<<1024, 256>>>(wmk);
    k1_mma<<<dim3(32, 8), 256, 90112>>>(x);
    k2_P_mma<<<dim3(32, 8), 128, 110592>>>();
    k3_att_mma<<<dim3(8, 8, 32), 256, 69632>>>();
    k5_gmz_mma<<<dim3(32, 8), 256, 53760>>>();
    k4_out_mma<<<dim3(32, 8), 128, 106496>>>(x, out);
}